// round 10
// baseline (speedup 1.0000x reference)
#include <cuda_runtime.h>
#include <cuda_fp16.h>
#include <cstdint>

// ============================ scratch (allocation-free) ============================
__device__ __half g_x16[4096 * 1024];
__device__ __half g_d16[2048 * 1024];
__device__ __half g_q16[4096 * 1024];
__device__ __half g_k16[2048 * 1024];
__device__ __half g_v16[2048 * 1024];
__device__ __half g_ao [4096 * 1024];
__device__ __half g_wq [1024 * 1024];
__device__ __half g_wk [1024 * 1024];
__device__ __half g_wv [1024 * 1024];
__device__ __half g_wo [1024 * 1024];

// ============================ PTX helpers (arch-generic) ============================
__device__ __forceinline__ uint32_t smem_u32(const void* p) {
    uint32_t a;
    asm("{ .reg .u64 t; cvta.to.shared.u64 t, %1; cvt.u32.u64 %0, t; }" : "=r"(a) : "l"(p));
    return a;
}
__device__ __forceinline__ void ldsm_x4(uint32_t& r0, uint32_t& r1, uint32_t& r2, uint32_t& r3,
                                        uint32_t addr) {
    asm volatile("ldmatrix.sync.aligned.m8n8.x4.shared.b16 {%0,%1,%2,%3}, [%4];"
                 : "=r"(r0), "=r"(r1), "=r"(r2), "=r"(r3) : "r"(addr));
}
__device__ __forceinline__ void ldsm_x4_t(uint32_t& r0, uint32_t& r1, uint32_t& r2, uint32_t& r3,
                                          uint32_t addr) {
    asm volatile("ldmatrix.sync.aligned.m8n8.x4.trans.shared.b16 {%0,%1,%2,%3}, [%4];"
                 : "=r"(r0), "=r"(r1), "=r"(r2), "=r"(r3) : "r"(addr));
}
__device__ __forceinline__ void mma_f16(float* d, const uint32_t* a, uint32_t b0, uint32_t b1) {
    asm volatile("mma.sync.aligned.m16n8k16.row.col.f32.f16.f16.f32 "
                 "{%0,%1,%2,%3}, {%4,%5,%6,%7}, {%8,%9}, {%0,%1,%2,%3};"
                 : "+f"(d[0]), "+f"(d[1]), "+f"(d[2]), "+f"(d[3])
                 : "r"(a[0]), "r"(a[1]), "r"(a[2]), "r"(a[3]), "r"(b0), "r"(b1));
}
__device__ __forceinline__ void cp_async16(uint32_t dst, const void* src) {
    asm volatile("cp.async.cg.shared.global [%0], [%1], 16;" :: "r"(dst), "l"(src) : "memory");
}
__device__ __forceinline__ void cp_commit() {
    asm volatile("cp.async.commit_group;" ::: "memory");
}

// ============================ conversions ============================
#define NX4 (4096 * 1024 / 4)
#define ND4 (2048 * 1024 / 4)
__global__ void cast_all_kernel(const float* __restrict__ x, const float* __restrict__ xd,
                                __half* __restrict__ x16, __half* __restrict__ d16) {
    int i = blockIdx.x * blockDim.x + threadIdx.x;
    const float* in; __half* out; int j;
    if (i < NX4)                { in = x;  out = x16; j = i; }
    else if (i < NX4 + ND4)     { in = xd; out = d16; j = i - NX4; }
    else return;
    float4 v = ((const float4*)in)[j];
    ((__half2*)out)[2 * j + 0] = __floats2half2_rn(v.x, v.y);
    ((__half2*)out)[2 * j + 1] = __floats2half2_rn(v.z, v.w);
}

// all 4 weights: [1024 k][1024 n] row-major -> [n][k] fp16, one launch (z selects)
__global__ void wsplit_all_kernel(const float* __restrict__ W0, const float* __restrict__ W1,
                                  const float* __restrict__ W2, const float* __restrict__ W3,
                                  __half* __restrict__ T0, __half* __restrict__ T1,
                                  __half* __restrict__ T2, __half* __restrict__ T3) {
    const int z = blockIdx.z;
    const float* W = (z == 0) ? W0 : (z == 1) ? W1 : (z == 2) ? W2 : W3;
    __half* T = (z == 0) ? T0 : (z == 1) ? T1 : (z == 2) ? T2 : T3;
    __shared__ float t[32][33];
    int x = blockIdx.x * 32 + threadIdx.x;
#pragma unroll
    for (int j = 0; j < 32; j += 8) {
        int kk = blockIdx.y * 32 + threadIdx.y + j;
        t[threadIdx.y + j][threadIdx.x] = W[kk * 1024 + x];
    }
    __syncthreads();
    int kx = blockIdx.y * 32 + threadIdx.x;
#pragma unroll
    for (int j = 0; j < 32; j += 8) {
        int n = blockIdx.x * 32 + threadIdx.y + j;
        T[n * 1024 + kx] = __float2half_rn(t[threadIdx.x][threadIdx.y + j]);
    }
}

// ============================ fp16 1-term GEMM core: 256x128 CTA, 64x64 warp ==========
// smem per stage: A 256x64 (36864 B) + B 128x64 (18432 B) = 55296 B; 3 stages = 165888 B
#define GTS      72
#define GA_BYTES (256 * GTS * 2)        // 36864
#define GB_BYTES (128 * GTS * 2)        // 18432
#define GSTAGE_B (GA_BYTES + GB_BYTES)  // 55296
#define G_SMEM   (3 * GSTAGE_B)         // 165888

struct GemmCore {
    // d[4][8][4]: warp tile 64x64 (4 m-frags x 8 n-frags)
    __device__ static void run(float d[4][8][4], const __half* A, const __half* B,
                               uint32_t sbase, int m0, int n0, int tid) {
        const int lane = tid & 31;
        const int wid  = tid >> 5;
        const int wm   = wid & 3;       // warp row (4) -> 64 rows each
        const int wn   = wid >> 2;      // warp col (2) -> 64 cols each

        auto issue_loads = [&](int c, int s) {
            const uint32_t abase = sbase + (uint32_t)(s * GSTAGE_B);
            // A: 256 rows x 64 cols = 2048 x 16B
#pragma unroll
            for (int it = 0; it < 8; it++) {
                const int idx = tid + it * 256;
                const int row = idx >> 3;
                const int q   = idx & 7;
                const void* src = A + ((size_t)(m0 + row) << 10) + c * 64 + q * 8;
                cp_async16(abase + (uint32_t)((row * GTS + q * 8) * 2), src);
            }
            // B: 128 rows x 64 cols = 1024 x 16B
            const uint32_t bbase = abase + (uint32_t)GA_BYTES;
#pragma unroll
            for (int it = 0; it < 4; it++) {
                const int idx = tid + it * 256;
                const int row = idx >> 3;
                const int q   = idx & 7;
                const void* src = B + ((size_t)(n0 + row) << 10) + c * 64 + q * 8;
                cp_async16(bbase + (uint32_t)((row * GTS + q * 8) * 2), src);
            }
            cp_commit();
        };

#pragma unroll
        for (int mt = 0; mt < 4; mt++)
#pragma unroll
            for (int nt = 0; nt < 8; nt++)
#pragma unroll
                for (int e = 0; e < 4; e++) d[mt][nt][e] = 0.0f;

        issue_loads(0, 0);
        issue_loads(1, 1);

        int ld_stage = 2, cur = 0;
        for (int c = 0; c < 16; c++) {
            asm volatile("cp.async.wait_group 1;" ::: "memory");
            __syncthreads();
            if (c + 2 < 16) issue_loads(c + 2, ld_stage);
            else            cp_commit();
            ld_stage = (ld_stage == 2) ? 0 : ld_stage + 1;

            const uint32_t stage = sbase + (uint32_t)(cur * GSTAGE_B);
            cur = (cur == 2) ? 0 : cur + 1;
            const uint32_t bbase = stage + (uint32_t)GA_BYTES;
#pragma unroll
            for (int ks = 0; ks < 4; ks++) {
                const int k16 = ks * 16;
                uint32_t af[4][4];
#pragma unroll
                for (int mt = 0; mt < 4; mt++) {
                    uint32_t addr = stage +
                        (uint32_t)(((wm * 64 + mt * 16 + (lane & 15)) * GTS
                                    + k16 + ((lane >> 4) * 8)) * 2);
                    ldsm_x4(af[mt][0], af[mt][1], af[mt][2], af[mt][3], addr);
                }
                const int mrow = lane >> 3;
                uint32_t bf[4][4];
#pragma unroll
                for (int g = 0; g < 4; g++) {
                    uint32_t addr = bbase +
                        (uint32_t)(((wn * 64 + g * 16 + (mrow & 2) * 4 + (lane & 7)) * GTS
                                    + k16 + ((mrow & 1) * 8)) * 2);
                    ldsm_x4(bf[g][0], bf[g][1], bf[g][2], bf[g][3], addr);
                }
#pragma unroll
                for (int mt = 0; mt < 4; mt++)
#pragma unroll
                    for (int nt = 0; nt < 8; nt++)
                        mma_f16(d[mt][nt], af[mt],
                                bf[nt >> 1][(nt & 1) * 2], bf[nt >> 1][(nt & 1) * 2 + 1]);
            }
        }
    }
};

// merged q/k/v projection: grid (8, 32); by<16: q, by<24: k, else v. fp16 out.
__global__ __launch_bounds__(256, 1)
void gemm_qkv_kernel(const __half* __restrict__ x16, const __half* __restrict__ d16,
                     const __half* __restrict__ wq, const __half* __restrict__ wk,
                     const __half* __restrict__ wv,
                     __half* __restrict__ q16, __half* __restrict__ k16,
                     __half* __restrict__ v16, float qscale) {
    extern __shared__ char smem[];
    const uint32_t sbase = smem_u32(smem);
    const int tid = threadIdx.x;
    const int by  = blockIdx.y;

    const __half* A; const __half* B; __half* C; float alpha; int m0;
    if (by < 16)      { A = x16; B = wq; C = q16; alpha = qscale; m0 = by * 256; }
    else if (by < 24) { A = d16; B = wk; C = k16; alpha = 1.0f;   m0 = (by - 16) * 256; }
    else              { A = d16; B = wv; C = v16; alpha = 1.0f;   m0 = (by - 24) * 256; }
    const int n0 = blockIdx.x * 128;

    float d[4][8][4];
    GemmCore::run(d, A, B, sbase, m0, n0, tid);

    const int lane = tid & 31, wid = tid >> 5, wm = wid & 3, wn = wid >> 2;
#pragma unroll
    for (int mt = 0; mt < 4; mt++) {
        const int row0 = m0 + wm * 64 + mt * 16 + (lane >> 2);
#pragma unroll
        for (int nt = 0; nt < 8; nt++) {
            const int col = n0 + wn * 64 + nt * 8 + (lane & 3) * 2;
            *(__half2*)(C + (size_t)row0 * 1024 + col) =
                __floats2half2_rn(d[mt][nt][0] * alpha, d[mt][nt][1] * alpha);
            *(__half2*)(C + (size_t)(row0 + 8) * 1024 + col) =
                __floats2half2_rn(d[mt][nt][2] * alpha, d[mt][nt][3] * alpha);
        }
    }
}

// output projection: fp32 + bias; grid (8, 16) = 128 CTAs (single wave)
__global__ __launch_bounds__(256, 1)
void gemm_o_kernel(const __half* __restrict__ A, const __half* __restrict__ B,
                   float* __restrict__ Cf, const float* __restrict__ bias) {
    extern __shared__ char smem[];
    const uint32_t sbase = smem_u32(smem);
    const int tid = threadIdx.x;
    const int m0 = blockIdx.y * 256;
    const int n0 = blockIdx.x * 128;

    float d[4][8][4];
    GemmCore::run(d, A, B, sbase, m0, n0, tid);

    const int lane = tid & 31, wid = tid >> 5, wm = wid & 3, wn = wid >> 2;
#pragma unroll
    for (int mt = 0; mt < 4; mt++) {
        const int row0 = m0 + wm * 64 + mt * 16 + (lane >> 2);
#pragma unroll
        for (int nt = 0; nt < 8; nt++) {
            const int col = n0 + wn * 64 + nt * 8 + (lane & 3) * 2;
            const float bx = bias[col], by = bias[col + 1];
            *(float2*)(Cf + (size_t)row0 * 1024 + col) =
                make_float2(d[mt][nt][0] + bx, d[mt][nt][1] + by);
            *(float2*)(Cf + (size_t)(row0 + 8) * 1024 + col) =
                make_float2(d[mt][nt][2] + bx, d[mt][nt][3] + by);
        }
    }
}

// ============================ tensor-core banded attention (unchanged) ===============
#define AQS     72
#define A_Q     0
#define A_KV    9216
#define A_TILE  4608
#define A_STAGE (2 * A_TILE)
#define ATTN_SMEM ((A_KV + 3 * A_STAGE) * 2)   // 73728 B

__global__ __launch_bounds__(256, 2)
void attn_mma_kernel(const __half* __restrict__ q,
                     const __half* __restrict__ k16,
                     const __half* __restrict__ v16,
                     __half* __restrict__ o) {
    extern __shared__ char smem[];
    const uint32_t sbase = smem_u32(smem);
    const int tid = threadIdx.x, lane = tid & 31, w = tid >> 5;
    const int qt = blockIdx.x, h = blockIdx.y, b = blockIdx.z;
    const int qi0 = qt * 128;

    int u_start = 0;
    { int lim = qi0 - 1089; if (lim > 0) u_start = ((lim + 63) >> 6) << 6; }

    {
#pragma unroll
        for (int it = 0; it < 4; it++) {
            int cid = tid + it * 256;
            int r = cid >> 3, qq = cid & 7;
            const void* src = q + ((size_t)(b * 2048 + qi0 + r) << 10) + h * 64 + qq * 8;
            uint32_t dst = sbase + (uint32_t)((A_Q + r * AQS + qq * 8) * 2);
            cp_async16(dst, src);
        }
        cp_commit();
    }

    auto issue_kv = [&](int u0, int s) {
#pragma unroll
        for (int it = 0; it < 4; it++) {
            int cid = tid + it * 256;
            int t = cid >> 9, r = (cid >> 3) & 63, qq = cid & 7;
            const __half* bp = t ? v16 : k16;
            const void* src = bp + ((size_t)(b * 1024 + u0 + r) << 10) + h * 64 + qq * 8;
            uint32_t dst = sbase + (uint32_t)((A_KV + s * A_STAGE + t * A_TILE + r * AQS + qq * 8) * 2);
            cp_async16(dst, src);
        }
        cp_commit();
    };
    issue_kv(u_start, 0);
    issue_kv(u_start + 64, 1);

    float d[8][4];
#pragma unroll
    for (int nt = 0; nt < 8; nt++)
#pragma unroll
        for (int e = 0; e < 4; e++) d[nt][e] = 0.0f;
    float dl[4] = {0.0f, 0.0f, 0.0f, 0.0f};

    const int i0 = qi0 + w * 16 + (lane >> 2);
    const int i1 = i0 + 8;
    const uint32_t ONES2 = 0x3C003C00u;

    int ld_stage = 2, cur = 0;
    for (int u0 = u_start; u0 < 1024; u0 += 64) {
        asm volatile("cp.async.wait_group 1;" ::: "memory");
        __syncthreads();
        if (u0 + 128 < 1024) issue_kv(u0 + 128, ld_stage);
        else                 cp_commit();
        ld_stage = (ld_stage == 2) ? 0 : ld_stage + 1;

        const uint32_t stg = sbase + (uint32_t)((A_KV + cur * A_STAGE) * 2);
        cur = (cur == 2) ? 0 : cur + 1;

        float s_[8][4];
#pragma unroll
        for (int nt = 0; nt < 8; nt++)
#pragma unroll
            for (int e = 0; e < 4; e++) s_[nt][e] = 0.0f;

#pragma unroll
        for (int ks = 0; ks < 4; ks++) {
            uint32_t af[4];
            ldsm_x4(af[0], af[1], af[2], af[3],
                sbase + (uint32_t)(((w * 16 + (lane & 15)) * AQS + ks * 16 + (lane >> 4) * 8) * 2));
            const int mrow = lane >> 3;
            uint32_t bf[4][4];
#pragma unroll
            for (int g = 0; g < 4; g++)
                ldsm_x4(bf[g][0], bf[g][1], bf[g][2], bf[g][3],
                    stg + (uint32_t)(((g * 16 + (mrow & 2) * 4 + (lane & 7)) * AQS
                                      + ks * 16 + (mrow & 1) * 8) * 2));
#pragma unroll
            for (int nt = 0; nt < 8; nt++)
                mma_f16(s_[nt], af, bf[nt >> 1][(nt & 1) * 2], bf[nt >> 1][(nt & 1) * 2 + 1]);
        }

        const bool t1_all  = (u0 >= qi0 + 125);
        const bool t1_none = (u0 < qi0 - 65);
        const bool t2_all  = (u0 >= qi0 - 899);
        const bool uniform = (t1_all || t1_none) && t2_all;

        uint32_t ph2[8][2];
        if (uniform) {
            const __half2 bias2 = __float2half2_rn(t1_all ? 1.0f : 0.0f);
#pragma unroll
            for (int nt = 0; nt < 8; nt++) {
                __half2 a0 = h2exp2(__hadd2(__floats2half2_rn(s_[nt][0], s_[nt][1]), bias2));
                __half2 a1 = h2exp2(__hadd2(__floats2half2_rn(s_[nt][2], s_[nt][3]), bias2));
                ph2[nt][0] = *reinterpret_cast<uint32_t*>(&a0);
                ph2[nt][1] = *reinterpret_cast<uint32_t*>(&a1);
            }
        } else {
#pragma unroll
            for (int nt = 0; nt < 8; nt++) {
                const int uc = u0 + nt * 8 + (lane & 3) * 2;
                float sv[4];
#pragma unroll
                for (int e = 0; e < 4; e++) {
                    const int u = uc + (e & 1);
                    const int i = (e < 2) ? i0 : i1;
                    const int mf = (u >= i - 2) + (u >= i - 1026);
                    sv[e] = (mf == 0) ? -1000.0f : s_[nt][e] + (mf == 2 ? 1.0f : 0.0f);
                }
                __half2 a0 = h2exp2(__floats2half2_rn(sv[0], sv[1]));
                __half2 a1 = h2exp2(__floats2half2_rn(sv[2], sv[3]));
                ph2[nt][0] = *reinterpret_cast<uint32_t*>(&a0);
                ph2[nt][1] = *reinterpret_cast<uint32_t*>(&a1);
            }
        }

#pragma unroll
        for (int ks = 0; ks < 4; ks++) {
            uint32_t ph[4];
            ph[0] = ph2[2 * ks][0];
            ph[1] = ph2[2 * ks][1];
            ph[2] = ph2[2 * ks + 1][0];
            ph[3] = ph2[2 * ks + 1][1];
            mma_f16(dl, ph, ONES2, ONES2);

            const uint32_t voff = (uint32_t)(((ks * 16 + ((lane >> 3) & 1) * 8 + (lane & 7)) * AQS) * 2)
                                + (uint32_t)((lane >> 4) * 16);
#pragma unroll
            for (int t = 0; t < 4; t++) {
                uint32_t vf[4];
                ldsm_x4_t(vf[0], vf[1], vf[2], vf[3],
                          stg + (uint32_t)(A_TILE * 2) + voff + (uint32_t)(t * 32));
                mma_f16(d[2 * t + 0], ph, vf[0], vf[1]);
                mma_f16(d[2 * t + 1], ph, vf[2], vf[3]);
            }
        }
    }

    const float inv0 = 1.0f / dl[0], inv1 = 1.0f / dl[2];
    const size_t row0 = (size_t)(b * 2048 + qi0 + w * 16 + (lane >> 2));
#pragma unroll
    for (int nt = 0; nt < 8; nt++) {
        const int col = h * 64 + nt * 8 + (lane & 3) * 2;
        *(__half2*)(o + row0 * 1024 + col)       = __floats2half2_rn(d[nt][0] * inv0, d[nt][1] * inv0);
        *(__half2*)(o + (row0 + 8) * 1024 + col) = __floats2half2_rn(d[nt][2] * inv1, d[nt][3] * inv1);
    }
}

// ============================ launch ============================
extern "C" void kernel_launch(void* const* d_in, const int* in_sizes, int n_in,
                              void* d_out, int out_size) {
    const float* x  = (const float*)d_in[0];
    const float* xd = (const float*)d_in[1];
    const float* Wq = (const float*)d_in[2];
    const float* Wk = (const float*)d_in[3];
    const float* Wv = (const float*)d_in[4];
    const float* Wo = (const float*)d_in[5];
    const float* bo = (const float*)d_in[6];
    float* out = (float*)d_out;

    __half *x16, *d16, *q16, *k16, *v16, *ao, *wq, *wk, *wv, *wo;
    cudaGetSymbolAddress((void**)&x16, g_x16);  cudaGetSymbolAddress((void**)&d16, g_d16);
    cudaGetSymbolAddress((void**)&q16, g_q16);  cudaGetSymbolAddress((void**)&k16, g_k16);
    cudaGetSymbolAddress((void**)&v16, g_v16);  cudaGetSymbolAddress((void**)&ao,  g_ao);
    cudaGetSymbolAddress((void**)&wq,  g_wq);   cudaGetSymbolAddress((void**)&wk,  g_wk);
    cudaGetSymbolAddress((void**)&wv,  g_wv);   cudaGetSymbolAddress((void**)&wo,  g_wo);

    cudaFuncSetAttribute(gemm_qkv_kernel, cudaFuncAttributeMaxDynamicSharedMemorySize, G_SMEM);
    cudaFuncSetAttribute(gemm_o_kernel,   cudaFuncAttributeMaxDynamicSharedMemorySize, G_SMEM);
    cudaFuncSetAttribute(attn_mma_kernel, cudaFuncAttributeMaxDynamicSharedMemorySize, ATTN_SMEM);

    const float qscale = 0.125f * 1.44269504088896341f;

    cast_all_kernel<<<(NX4 + ND4 + 255) / 256, 256>>>(x, xd, x16, d16);
    wsplit_all_kernel<<<dim3(32, 32, 4), dim3(32, 8)>>>(Wq, Wk, Wv, Wo, wq, wk, wv, wo);

    gemm_qkv_kernel<<<dim3(8, 32), 256, G_SMEM>>>(x16, d16, wq, wk, wv, q16, k16, v16, qscale);

    attn_mma_kernel<<<dim3(16, 16, 2), 256, ATTN_SMEM>>>(q16, k16, v16, ao);

    gemm_o_kernel<<<dim3(8, 16), 256, G_SMEM>>>(ao, wo, out, bo);
}

// round 11
// speedup vs baseline: 1.0103x; 1.0103x over previous
#include <cuda_runtime.h>
#include <cuda_fp16.h>
#include <cstdint>

// ============================ scratch (allocation-free) ============================
__device__ __half g_x16[4096 * 1024];
__device__ __half g_d16[2048 * 1024];
__device__ __half g_q16[4096 * 1024];
__device__ __half g_k16[2048 * 1024];
__device__ __half g_v16[2048 * 1024];
__device__ __half g_ao [4096 * 1024];
__device__ __half g_wq [1024 * 1024];
__device__ __half g_wk [1024 * 1024];
__device__ __half g_wv [1024 * 1024];
__device__ __half g_wo [1024 * 1024];

// ============================ PTX helpers (arch-generic) ============================
__device__ __forceinline__ uint32_t smem_u32(const void* p) {
    uint32_t a;
    asm("{ .reg .u64 t; cvta.to.shared.u64 t, %1; cvt.u32.u64 %0, t; }" : "=r"(a) : "l"(p));
    return a;
}
__device__ __forceinline__ void ldsm_x4(uint32_t& r0, uint32_t& r1, uint32_t& r2, uint32_t& r3,
                                        uint32_t addr) {
    asm volatile("ldmatrix.sync.aligned.m8n8.x4.shared.b16 {%0,%1,%2,%3}, [%4];"
                 : "=r"(r0), "=r"(r1), "=r"(r2), "=r"(r3) : "r"(addr));
}
__device__ __forceinline__ void ldsm_x4_t(uint32_t& r0, uint32_t& r1, uint32_t& r2, uint32_t& r3,
                                          uint32_t addr) {
    asm volatile("ldmatrix.sync.aligned.m8n8.x4.trans.shared.b16 {%0,%1,%2,%3}, [%4];"
                 : "=r"(r0), "=r"(r1), "=r"(r2), "=r"(r3) : "r"(addr));
}
__device__ __forceinline__ void mma_f16(float* d, const uint32_t* a, uint32_t b0, uint32_t b1) {
    asm volatile("mma.sync.aligned.m16n8k16.row.col.f32.f16.f16.f32 "
                 "{%0,%1,%2,%3}, {%4,%5,%6,%7}, {%8,%9}, {%0,%1,%2,%3};"
                 : "+f"(d[0]), "+f"(d[1]), "+f"(d[2]), "+f"(d[3])
                 : "r"(a[0]), "r"(a[1]), "r"(a[2]), "r"(a[3]), "r"(b0), "r"(b1));
}
__device__ __forceinline__ void cp_async16(uint32_t dst, const void* src) {
    asm volatile("cp.async.cg.shared.global [%0], [%1], 16;" :: "r"(dst), "l"(src) : "memory");
}
__device__ __forceinline__ void cp_commit() {
    asm volatile("cp.async.commit_group;" ::: "memory");
}

// ============================ conversions ============================
#define NX4 (4096 * 1024 / 4)
#define ND4 (2048 * 1024 / 4)
__global__ void cast_all_kernel(const float* __restrict__ x, const float* __restrict__ xd,
                                __half* __restrict__ x16, __half* __restrict__ d16) {
    int i = blockIdx.x * blockDim.x + threadIdx.x;
    const float* in; __half* out; int j;
    if (i < NX4)                { in = x;  out = x16; j = i; }
    else if (i < NX4 + ND4)     { in = xd; out = d16; j = i - NX4; }
    else return;
    float4 v = ((const float4*)in)[j];
    ((__half2*)out)[2 * j + 0] = __floats2half2_rn(v.x, v.y);
    ((__half2*)out)[2 * j + 1] = __floats2half2_rn(v.z, v.w);
}

// all 4 weights: [1024 k][1024 n] row-major -> [n][k] fp16, one launch (z selects)
__global__ void wsplit_all_kernel(const float* __restrict__ W0, const float* __restrict__ W1,
                                  const float* __restrict__ W2, const float* __restrict__ W3,
                                  __half* __restrict__ T0, __half* __restrict__ T1,
                                  __half* __restrict__ T2, __half* __restrict__ T3) {
    const int z = blockIdx.z;
    const float* W = (z == 0) ? W0 : (z == 1) ? W1 : (z == 2) ? W2 : W3;
    __half* T = (z == 0) ? T0 : (z == 1) ? T1 : (z == 2) ? T2 : T3;
    __shared__ float t[32][33];
    int x = blockIdx.x * 32 + threadIdx.x;
#pragma unroll
    for (int j = 0; j < 32; j += 8) {
        int kk = blockIdx.y * 32 + threadIdx.y + j;
        t[threadIdx.y + j][threadIdx.x] = W[kk * 1024 + x];
    }
    __syncthreads();
    int kx = blockIdx.y * 32 + threadIdx.x;
#pragma unroll
    for (int j = 0; j < 32; j += 8) {
        int n = blockIdx.x * 32 + threadIdx.y + j;
        T[n * 1024 + kx] = __float2half_rn(t[threadIdx.x][threadIdx.y + j]);
    }
}

// ============================ fp16 1-term GEMM core (R9 config: 128x128, 3-stage) =====
#define GTS      72
#define GTILE_B  (128 * GTS * 2)        // 18432
#define G_SMEM   (6 * GTILE_B)          // A,B x 3 stages = 110592

struct GemmCore {
    __device__ static void run(float d[2][8][4], const __half* A, const __half* B,
                               uint32_t sbase, int m0, int n0, int tid) {
        const int lane = tid & 31;
        const int wid  = tid >> 5;
        const int wm   = wid & 3;
        const int wn   = wid >> 2;

        auto issue_loads = [&](int c, int s) {
#pragma unroll
            for (int it = 0; it < 8; it++) {
                const int part = it >> 2;               // 0=A, 1=B
                const int w    = tid + (it & 3) * 256;
                const int row  = w >> 3;
                const int q    = w & 7;
                const __half* base = part ? B : A;
                const int grow = part ? (n0 + row) : (m0 + row);
                const void* src = base + ((size_t)grow << 10) + c * 64 + q * 8;
                uint32_t dst = sbase + (uint32_t)((s * 2 + part) * GTILE_B)
                             + (uint32_t)((row * GTS + q * 8) * 2);
                cp_async16(dst, src);
            }
            cp_commit();
        };

#pragma unroll
        for (int mt = 0; mt < 2; mt++)
#pragma unroll
            for (int nt = 0; nt < 8; nt++)
#pragma unroll
                for (int e = 0; e < 4; e++) d[mt][nt][e] = 0.0f;

        issue_loads(0, 0);
        issue_loads(1, 1);

        int ld_stage = 2, cur = 0;
        for (int c = 0; c < 16; c++) {
            asm volatile("cp.async.wait_group 1;" ::: "memory");
            __syncthreads();
            if (c + 2 < 16) issue_loads(c + 2, ld_stage);
            else            cp_commit();
            ld_stage = (ld_stage == 2) ? 0 : ld_stage + 1;

            const uint32_t stage = sbase + (uint32_t)(cur * 2 * GTILE_B);
            cur = (cur == 2) ? 0 : cur + 1;
            const uint32_t bbase = stage + (uint32_t)GTILE_B;
#pragma unroll
            for (int ks = 0; ks < 4; ks++) {
                const int k16 = ks * 16;
                uint32_t af[2][4];
#pragma unroll
                for (int mt = 0; mt < 2; mt++) {
                    uint32_t addr = stage +
                        (uint32_t)(((wm * 32 + mt * 16 + (lane & 15)) * GTS
                                    + k16 + ((lane >> 4) * 8)) * 2);
                    ldsm_x4(af[mt][0], af[mt][1], af[mt][2], af[mt][3], addr);
                }
                const int mrow = lane >> 3;
                uint32_t bf[4][4];
#pragma unroll
                for (int g = 0; g < 4; g++) {
                    uint32_t addr = bbase +
                        (uint32_t)(((wn * 64 + g * 16 + (mrow & 2) * 4 + (lane & 7)) * GTS
                                    + k16 + ((mrow & 1) * 8)) * 2);
                    ldsm_x4(bf[g][0], bf[g][1], bf[g][2], bf[g][3], addr);
                }
#pragma unroll
                for (int mt = 0; mt < 2; mt++)
#pragma unroll
                    for (int nt = 0; nt < 8; nt++)
                        mma_f16(d[mt][nt], af[mt],
                                bf[nt >> 1][(nt & 1) * 2], bf[nt >> 1][(nt & 1) * 2 + 1]);
            }
        }
    }
};

// merged q/k/v projection: grid (8, 64); by<32: q, by<48: k, else v. fp16 out.
__global__ __launch_bounds__(256, 2)
void gemm_qkv_kernel(const __half* __restrict__ x16, const __half* __restrict__ d16,
                     const __half* __restrict__ wq, const __half* __restrict__ wk,
                     const __half* __restrict__ wv,
                     __half* __restrict__ q16, __half* __restrict__ k16,
                     __half* __restrict__ v16, float qscale) {
    extern __shared__ char smem[];
    const uint32_t sbase = smem_u32(smem);
    const int tid = threadIdx.x;
    const int by  = blockIdx.y;

    const __half* A; const __half* B; __half* C; float alpha; int m0;
    if (by < 32)      { A = x16; B = wq; C = q16; alpha = qscale; m0 = by * 128; }
    else if (by < 48) { A = d16; B = wk; C = k16; alpha = 1.0f;   m0 = (by - 32) * 128; }
    else              { A = d16; B = wv; C = v16; alpha = 1.0f;   m0 = (by - 48) * 128; }
    const int n0 = blockIdx.x * 128;

    float d[2][8][4];
    GemmCore::run(d, A, B, sbase, m0, n0, tid);

    const int lane = tid & 31, wid = tid >> 5, wm = wid & 3, wn = wid >> 2;
#pragma unroll
    for (int mt = 0; mt < 2; mt++) {
        const int row0 = m0 + wm * 32 + mt * 16 + (lane >> 2);
#pragma unroll
        for (int nt = 0; nt < 8; nt++) {
            const int col = n0 + wn * 64 + nt * 8 + (lane & 3) * 2;
            *(__half2*)(C + (size_t)row0 * 1024 + col) =
                __floats2half2_rn(d[mt][nt][0] * alpha, d[mt][nt][1] * alpha);
            *(__half2*)(C + (size_t)(row0 + 8) * 1024 + col) =
                __floats2half2_rn(d[mt][nt][2] * alpha, d[mt][nt][3] * alpha);
        }
    }
}

// output projection: fp32 + bias
__global__ __launch_bounds__(256, 2)
void gemm_o_kernel(const __half* __restrict__ A, const __half* __restrict__ B,
                   float* __restrict__ Cf, const float* __restrict__ bias) {
    extern __shared__ char smem[];
    const uint32_t sbase = smem_u32(smem);
    const int tid = threadIdx.x;
    const int m0 = blockIdx.y * 128;
    const int n0 = blockIdx.x * 128;

    float d[2][8][4];
    GemmCore::run(d, A, B, sbase, m0, n0, tid);

    const int lane = tid & 31, wid = tid >> 5, wm = wid & 3, wn = wid >> 2;
#pragma unroll
    for (int mt = 0; mt < 2; mt++) {
        const int row0 = m0 + wm * 32 + mt * 16 + (lane >> 2);
#pragma unroll
        for (int nt = 0; nt < 8; nt++) {
            const int col = n0 + wn * 64 + nt * 8 + (lane & 3) * 2;
            const float bx = bias[col], by = bias[col + 1];
            *(float2*)(Cf + (size_t)row0 * 1024 + col) =
                make_float2(d[mt][nt][0] + bx, d[mt][nt][1] + by);
            *(float2*)(Cf + (size_t)(row0 + 8) * 1024 + col) =
                make_float2(d[mt][nt][2] + bx, d[mt][nt][3] + by);
        }
    }
}

// ============================ tensor-core banded attention ============================
// Q fragments hoisted to registers; exp/pack fused into the PV ks-loop.
#define AQS     72
#define A_Q     0
#define A_KV    9216
#define A_TILE  4608
#define A_STAGE (2 * A_TILE)
#define ATTN_SMEM ((A_KV + 3 * A_STAGE) * 2)   // 73728 B

__global__ __launch_bounds__(256, 2)
void attn_mma_kernel(const __half* __restrict__ q,
                     const __half* __restrict__ k16,
                     const __half* __restrict__ v16,
                     __half* __restrict__ o) {
    extern __shared__ char smem[];
    const uint32_t sbase = smem_u32(smem);
    const int tid = threadIdx.x, lane = tid & 31, w = tid >> 5;
    const int qt = blockIdx.x, h = blockIdx.y, b = blockIdx.z;
    const int qi0 = qt * 128;

    int u_start = 0;
    { int lim = qi0 - 1089; if (lim > 0) u_start = ((lim + 63) >> 6) << 6; }

    // Q load (group 0)
    {
#pragma unroll
        for (int it = 0; it < 4; it++) {
            int cid = tid + it * 256;
            int r = cid >> 3, qq = cid & 7;
            const void* src = q + ((size_t)(b * 2048 + qi0 + r) << 10) + h * 64 + qq * 8;
            uint32_t dst = sbase + (uint32_t)((A_Q + r * AQS + qq * 8) * 2);
            cp_async16(dst, src);
        }
        cp_commit();
    }

    auto issue_kv = [&](int u0, int s) {
#pragma unroll
        for (int it = 0; it < 4; it++) {
            int cid = tid + it * 256;
            int t = cid >> 9, r = (cid >> 3) & 63, qq = cid & 7;
            const __half* bp = t ? v16 : k16;
            const void* src = bp + ((size_t)(b * 1024 + u0 + r) << 10) + h * 64 + qq * 8;
            uint32_t dst = sbase + (uint32_t)((A_KV + s * A_STAGE + t * A_TILE + r * AQS + qq * 8) * 2);
            cp_async16(dst, src);
        }
        cp_commit();
    };
    issue_kv(u_start, 0);        // group 1
    issue_kv(u_start + 64, 1);   // group 2

    // ---- hoist Q fragments: wait for group 0 only, then load once ----
    uint32_t qf[4][4];
    asm volatile("cp.async.wait_group 2;" ::: "memory");
    __syncthreads();
#pragma unroll
    for (int ks = 0; ks < 4; ks++)
        ldsm_x4(qf[ks][0], qf[ks][1], qf[ks][2], qf[ks][3],
            sbase + (uint32_t)(((w * 16 + (lane & 15)) * AQS + ks * 16 + (lane >> 4) * 8) * 2));

    float d[8][4];
#pragma unroll
    for (int nt = 0; nt < 8; nt++)
#pragma unroll
        for (int e = 0; e < 4; e++) d[nt][e] = 0.0f;
    float dl[4] = {0.0f, 0.0f, 0.0f, 0.0f};

    const int i0 = qi0 + w * 16 + (lane >> 2);
    const int i1 = i0 + 8;
    const uint32_t ONES2 = 0x3C003C00u;

    int ld_stage = 2, cur = 0;
    for (int u0 = u_start; u0 < 1024; u0 += 64) {
        asm volatile("cp.async.wait_group 1;" ::: "memory");
        __syncthreads();
        if (u0 + 128 < 1024) issue_kv(u0 + 128, ld_stage);
        else                 cp_commit();
        ld_stage = (ld_stage == 2) ? 0 : ld_stage + 1;

        const uint32_t stg = sbase + (uint32_t)((A_KV + cur * A_STAGE) * 2);
        cur = (cur == 2) ? 0 : cur + 1;

        // ---- S = Q * K (Q from registers) ----
        float s_[8][4];
#pragma unroll
        for (int nt = 0; nt < 8; nt++)
#pragma unroll
            for (int e = 0; e < 4; e++) s_[nt][e] = 0.0f;

#pragma unroll
        for (int ks = 0; ks < 4; ks++) {
            const int mrow = lane >> 3;
            uint32_t bf[4][4];
#pragma unroll
            for (int g = 0; g < 4; g++)
                ldsm_x4(bf[g][0], bf[g][1], bf[g][2], bf[g][3],
                    stg + (uint32_t)(((g * 16 + (mrow & 2) * 4 + (lane & 7)) * AQS
                                      + ks * 16 + (mrow & 1) * 8) * 2));
#pragma unroll
            for (int nt = 0; nt < 8; nt++)
                mma_f16(s_[nt], qf[ks], bf[nt >> 1][(nt & 1) * 2], bf[nt >> 1][(nt & 1) * 2 + 1]);
        }

        // ---- mask fold (kept in fp32 s_), then fused exp+pack+PV per ks ----
        const bool t1_all  = (u0 >= qi0 + 125);
        const bool t1_none = (u0 < qi0 - 65);
        const bool t2_all  = (u0 >= qi0 - 899);
        const bool uniform = (t1_all || t1_none) && t2_all;
        const float ubias  = t1_all ? 1.0f : 0.0f;

        if (!uniform) {
#pragma unroll
            for (int nt = 0; nt < 8; nt++) {
                const int uc = u0 + nt * 8 + (lane & 3) * 2;
#pragma unroll
                for (int e = 0; e < 4; e++) {
                    const int u = uc + (e & 1);
                    const int i = (e < 2) ? i0 : i1;
                    const int mf = (u >= i - 2) + (u >= i - 1026);
                    s_[nt][e] = (mf == 0) ? -1000.0f : s_[nt][e] + (mf == 2 ? 1.0f : 0.0f);
                }
            }
        }

#pragma unroll
        for (int ks = 0; ks < 4; ks++) {
            const int n0f = 2 * ks, n1f = 2 * ks + 1;
            uint32_t ph[4];
            {
                __half2 a0, a1, a2, a3;
                if (uniform) {
                    a0 = h2exp2(__floats2half2_rn(s_[n0f][0] + ubias, s_[n0f][1] + ubias));
                    a1 = h2exp2(__floats2half2_rn(s_[n0f][2] + ubias, s_[n0f][3] + ubias));
                    a2 = h2exp2(__floats2half2_rn(s_[n1f][0] + ubias, s_[n1f][1] + ubias));
                    a3 = h2exp2(__floats2half2_rn(s_[n1f][2] + ubias, s_[n1f][3] + ubias));
                } else {
                    a0 = h2exp2(__floats2half2_rn(s_[n0f][0], s_[n0f][1]));
                    a1 = h2exp2(__floats2half2_rn(s_[n0f][2], s_[n0f][3]));
                    a2 = h2exp2(__floats2half2_rn(s_[n1f][0], s_[n1f][1]));
                    a3 = h2exp2(__floats2half2_rn(s_[n1f][2], s_[n1f][3]));
                }
                ph[0] = *reinterpret_cast<uint32_t*>(&a0);
                ph[1] = *reinterpret_cast<uint32_t*>(&a1);
                ph[2] = *reinterpret_cast<uint32_t*>(&a2);
                ph[3] = *reinterpret_cast<uint32_t*>(&a3);
            }
            mma_f16(dl, ph, ONES2, ONES2);   // row sums

            const uint32_t voff = (uint32_t)(((ks * 16 + ((lane >> 3) & 1) * 8 + (lane & 7)) * AQS) * 2)
                                + (uint32_t)((lane >> 4) * 16);
#pragma unroll
            for (int t = 0; t < 4; t++) {
                uint32_t vf[4];
                ldsm_x4_t(vf[0], vf[1], vf[2], vf[3],
                          stg + (uint32_t)(A_TILE * 2) + voff + (uint32_t)(t * 32));
                mma_f16(d[2 * t + 0], ph, vf[0], vf[1]);
                mma_f16(d[2 * t + 1], ph, vf[2], vf[3]);
            }
        }
    }

    // ---- epilogue ----
    const float inv0 = 1.0f / dl[0], inv1 = 1.0f / dl[2];
    const size_t row0 = (size_t)(b * 2048 + qi0 + w * 16 + (lane >> 2));
#pragma unroll
    for (int nt = 0; nt < 8; nt++) {
        const int col = h * 64 + nt * 8 + (lane & 3) * 2;
        *(__half2*)(o + row0 * 1024 + col)       = __floats2half2_rn(d[nt][0] * inv0, d[nt][1] * inv0);
        *(__half2*)(o + (row0 + 8) * 1024 + col) = __floats2half2_rn(d[nt][2] * inv1, d[nt][3] * inv1);
    }
}

// ============================ launch ============================
extern "C" void kernel_launch(void* const* d_in, const int* in_sizes, int n_in,
                              void* d_out, int out_size) {
    const float* x  = (const float*)d_in[0];
    const float* xd = (const float*)d_in[1];
    const float* Wq = (const float*)d_in[2];
    const float* Wk = (const float*)d_in[3];
    const float* Wv = (const float*)d_in[4];
    const float* Wo = (const float*)d_in[5];
    const float* bo = (const float*)d_in[6];
    float* out = (float*)d_out;

    __half *x16, *d16, *q16, *k16, *v16, *ao, *wq, *wk, *wv, *wo;
    cudaGetSymbolAddress((void**)&x16, g_x16);  cudaGetSymbolAddress((void**)&d16, g_d16);
    cudaGetSymbolAddress((void**)&q16, g_q16);  cudaGetSymbolAddress((void**)&k16, g_k16);
    cudaGetSymbolAddress((void**)&v16, g_v16);  cudaGetSymbolAddress((void**)&ao,  g_ao);
    cudaGetSymbolAddress((void**)&wq,  g_wq);   cudaGetSymbolAddress((void**)&wk,  g_wk);
    cudaGetSymbolAddress((void**)&wv,  g_wv);   cudaGetSymbolAddress((void**)&wo,  g_wo);

    cudaFuncSetAttribute(gemm_qkv_kernel, cudaFuncAttributeMaxDynamicSharedMemorySize, G_SMEM);
    cudaFuncSetAttribute(gemm_o_kernel,   cudaFuncAttributeMaxDynamicSharedMemorySize, G_SMEM);
    cudaFuncSetAttribute(attn_mma_kernel, cudaFuncAttributeMaxDynamicSharedMemorySize, ATTN_SMEM);

    const float qscale = 0.125f * 1.44269504088896341f;

    cast_all_kernel<<<(NX4 + ND4 + 255) / 256, 256>>>(x, xd, x16, d16);
    wsplit_all_kernel<<<dim3(32, 32, 4), dim3(32, 8)>>>(Wq, Wk, Wv, Wo, wq, wk, wv, wo);

    gemm_qkv_kernel<<<dim3(8, 64), 256, G_SMEM>>>(x16, d16, wq, wk, wv, q16, k16, v16, qscale);

    attn_mma_kernel<<<dim3(16, 16, 2), 256, ATTN_SMEM>>>(q16, k16, v16, ao);

    gemm_o_kernel<<<dim3(8, 32), 256, G_SMEM>>>(ao, wo, out, bo);
}

// round 13
// speedup vs baseline: 1.0266x; 1.0162x over previous
#include <cuda_runtime.h>
#include <cuda_fp16.h>
#include <cstdint>

// ============================ scratch (allocation-free) ============================
__device__ __half g_x16[4096 * 1024];
__device__ __half g_d16[2048 * 1024];
__device__ __half g_q16[4096 * 1024];
__device__ __half g_k16[2048 * 1024];
__device__ __half g_v16[2048 * 1024];
__device__ __half g_ao [4096 * 1024];
__device__ __half g_wq [1024 * 1024];
__device__ __half g_wk [1024 * 1024];
__device__ __half g_wv [1024 * 1024];
__device__ __half g_wo [1024 * 1024];

// ============================ PTX helpers (arch-generic) ============================
__device__ __forceinline__ uint32_t smem_u32(const void* p) {
    uint32_t a;
    asm("{ .reg .u64 t; cvta.to.shared.u64 t, %1; cvt.u32.u64 %0, t; }" : "=r"(a) : "l"(p));
    return a;
}
__device__ __forceinline__ void ldsm_x4(uint32_t& r0, uint32_t& r1, uint32_t& r2, uint32_t& r3,
                                        uint32_t addr) {
    asm volatile("ldmatrix.sync.aligned.m8n8.x4.shared.b16 {%0,%1,%2,%3}, [%4];"
                 : "=r"(r0), "=r"(r1), "=r"(r2), "=r"(r3) : "r"(addr));
}
__device__ __forceinline__ void ldsm_x4_t(uint32_t& r0, uint32_t& r1, uint32_t& r2, uint32_t& r3,
                                          uint32_t addr) {
    asm volatile("ldmatrix.sync.aligned.m8n8.x4.trans.shared.b16 {%0,%1,%2,%3}, [%4];"
                 : "=r"(r0), "=r"(r1), "=r"(r2), "=r"(r3) : "r"(addr));
}
__device__ __forceinline__ void mma_f16(float* d, const uint32_t* a, uint32_t b0, uint32_t b1) {
    asm volatile("mma.sync.aligned.m16n8k16.row.col.f32.f16.f16.f32 "
                 "{%0,%1,%2,%3}, {%4,%5,%6,%7}, {%8,%9}, {%0,%1,%2,%3};"
                 : "+f"(d[0]), "+f"(d[1]), "+f"(d[2]), "+f"(d[3])
                 : "r"(a[0]), "r"(a[1]), "r"(a[2]), "r"(a[3]), "r"(b0), "r"(b1));
}
__device__ __forceinline__ void cp_async16(uint32_t dst, const void* src) {
    asm volatile("cp.async.cg.shared.global [%0], [%1], 16;" :: "r"(dst), "l"(src) : "memory");
}
__device__ __forceinline__ void cp_commit() {
    asm volatile("cp.async.commit_group;" ::: "memory");
}

// ============================ fused conversion (one launch) ============================
#define NX4 (4096 * 1024 / 4)
#define ND4 (2048 * 1024 / 4)
#define NCAST ((NX4 + ND4) / 256)          // 6144 blocks for casting
__global__ void prep_kernel(const float* __restrict__ x, const float* __restrict__ xd,
                            const float* __restrict__ W0, const float* __restrict__ W1,
                            const float* __restrict__ W2, const float* __restrict__ W3,
                            __half* __restrict__ x16, __half* __restrict__ d16,
                            __half* __restrict__ T0, __half* __restrict__ T1,
                            __half* __restrict__ T2, __half* __restrict__ T3) {
    const int bx = blockIdx.x;
    const int tid = threadIdx.x;
    if (bx < NCAST) {
        int i = bx * 256 + tid;
        const float* in; __half* out; int j;
        if (i < NX4) { in = x;  out = x16; j = i; }
        else         { in = xd; out = d16; j = i - NX4; }
        float4 v = ((const float4*)in)[j];
        ((__half2*)out)[2 * j + 0] = __floats2half2_rn(v.x, v.y);
        ((__half2*)out)[2 * j + 1] = __floats2half2_rn(v.z, v.w);
        return;
    }
    // weight transpose: idx decodes (z, by, bx32)
    const int idx = bx - NCAST;                 // 0..4095
    const int z   = idx >> 10;
    const int byy = (idx >> 5) & 31;
    const int bxx = idx & 31;
    const float* W = (z == 0) ? W0 : (z == 1) ? W1 : (z == 2) ? W2 : W3;
    __half* T = (z == 0) ? T0 : (z == 1) ? T1 : (z == 2) ? T2 : T3;
    const int tx = tid & 31, ty = tid >> 5;     // 32 x 8
    __shared__ float t[32][33];
    int xcol = bxx * 32 + tx;
#pragma unroll
    for (int j = 0; j < 32; j += 8) {
        int kk = byy * 32 + ty + j;
        t[ty + j][tx] = W[kk * 1024 + xcol];
    }
    __syncthreads();
    int kx = byy * 32 + tx;
#pragma unroll
    for (int j = 0; j < 32; j += 8) {
        int n = bxx * 32 + ty + j;
        T[n * 1024 + kx] = __float2half_rn(t[tx][ty + j]);
    }
}

// ============================ fp16 1-term GEMM core (R9: 128x128, 3-stage) ============
#define GTS      72
#define GTILE_B  (128 * GTS * 2)        // 18432
#define G_SMEM   (6 * GTILE_B)          // 110592

struct GemmCore {
    __device__ static void run(float d[2][8][4], const __half* A, const __half* B,
                               uint32_t sbase, int m0, int n0, int tid) {
        const int lane = tid & 31;
        const int wid  = tid >> 5;
        const int wm   = wid & 3;
        const int wn   = wid >> 2;

        auto issue_loads = [&](int c, int s) {
#pragma unroll
            for (int it = 0; it < 8; it++) {
                const int part = it >> 2;               // 0=A, 1=B
                const int w    = tid + (it & 3) * 256;
                const int row  = w >> 3;
                const int q    = w & 7;
                const __half* base = part ? B : A;
                const int grow = part ? (n0 + row) : (m0 + row);
                const void* src = base + ((size_t)grow << 10) + c * 64 + q * 8;
                uint32_t dst = sbase + (uint32_t)((s * 2 + part) * GTILE_B)
                             + (uint32_t)((row * GTS + q * 8) * 2);
                cp_async16(dst, src);
            }
            cp_commit();
        };

#pragma unroll
        for (int mt = 0; mt < 2; mt++)
#pragma unroll
            for (int nt = 0; nt < 8; nt++)
#pragma unroll
                for (int e = 0; e < 4; e++) d[mt][nt][e] = 0.0f;

        issue_loads(0, 0);
        issue_loads(1, 1);

        int ld_stage = 2, cur = 0;
        for (int c = 0; c < 16; c++) {
            asm volatile("cp.async.wait_group 1;" ::: "memory");
            __syncthreads();
            if (c + 2 < 16) issue_loads(c + 2, ld_stage);
            else            cp_commit();
            ld_stage = (ld_stage == 2) ? 0 : ld_stage + 1;

            const uint32_t stage = sbase + (uint32_t)(cur * 2 * GTILE_B);
            cur = (cur == 2) ? 0 : cur + 1;
            const uint32_t bbase = stage + (uint32_t)GTILE_B;
#pragma unroll
            for (int ks = 0; ks < 4; ks++) {
                const int k16 = ks * 16;
                uint32_t af[2][4];
#pragma unroll
                for (int mt = 0; mt < 2; mt++) {
                    uint32_t addr = stage +
                        (uint32_t)(((wm * 32 + mt * 16 + (lane & 15)) * GTS
                                    + k16 + ((lane >> 4) * 8)) * 2);
                    ldsm_x4(af[mt][0], af[mt][1], af[mt][2], af[mt][3], addr);
                }
                const int mrow = lane >> 3;
                uint32_t bf[4][4];
#pragma unroll
                for (int g = 0; g < 4; g++) {
                    uint32_t addr = bbase +
                        (uint32_t)(((wn * 64 + g * 16 + (mrow & 2) * 4 + (lane & 7)) * GTS
                                    + k16 + ((mrow & 1) * 8)) * 2);
                    ldsm_x4(bf[g][0], bf[g][1], bf[g][2], bf[g][3], addr);
                }
#pragma unroll
                for (int mt = 0; mt < 2; mt++)
#pragma unroll
                    for (int nt = 0; nt < 8; nt++)
                        mma_f16(d[mt][nt], af[mt],
                                bf[nt >> 1][(nt & 1) * 2], bf[nt >> 1][(nt & 1) * 2 + 1]);
            }
        }
    }
};

// merged q/k/v projection: grid (8, 64); by<32: q, by<48: k, else v. fp16 out.
__global__ __launch_bounds__(256, 2)
void gemm_qkv_kernel(const __half* __restrict__ x16, const __half* __restrict__ d16,
                     const __half* __restrict__ wq, const __half* __restrict__ wk,
                     const __half* __restrict__ wv,
                     __half* __restrict__ q16, __half* __restrict__ k16,
                     __half* __restrict__ v16, float qscale) {
    extern __shared__ char smem[];
    const uint32_t sbase = smem_u32(smem);
    const int tid = threadIdx.x;
    const int by  = blockIdx.y;

    const __half* A; const __half* B; __half* C; float alpha; int m0;
    if (by < 32)      { A = x16; B = wq; C = q16; alpha = qscale; m0 = by * 128; }
    else if (by < 48) { A = d16; B = wk; C = k16; alpha = 1.0f;   m0 = (by - 32) * 128; }
    else              { A = d16; B = wv; C = v16; alpha = 1.0f;   m0 = (by - 48) * 128; }
    const int n0 = blockIdx.x * 128;

    float d[2][8][4];
    GemmCore::run(d, A, B, sbase, m0, n0, tid);

    const int lane = tid & 31, wid = tid >> 5, wm = wid & 3, wn = wid >> 2;
#pragma unroll
    for (int mt = 0; mt < 2; mt++) {
        const int row0 = m0 + wm * 32 + mt * 16 + (lane >> 2);
#pragma unroll
        for (int nt = 0; nt < 8; nt++) {
            const int col = n0 + wn * 64 + nt * 8 + (lane & 3) * 2;
            *(__half2*)(C + (size_t)row0 * 1024 + col) =
                __floats2half2_rn(d[mt][nt][0] * alpha, d[mt][nt][1] * alpha);
            *(__half2*)(C + (size_t)(row0 + 8) * 1024 + col) =
                __floats2half2_rn(d[mt][nt][2] * alpha, d[mt][nt][3] * alpha);
        }
    }
}

// output projection: fp32 + bias
__global__ __launch_bounds__(256, 2)
void gemm_o_kernel(const __half* __restrict__ A, const __half* __restrict__ B,
                   float* __restrict__ Cf, const float* __restrict__ bias) {
    extern __shared__ char smem[];
    const uint32_t sbase = smem_u32(smem);
    const int tid = threadIdx.x;
    const int m0 = blockIdx.y * 128;
    const int n0 = blockIdx.x * 128;

    float d[2][8][4];
    GemmCore::run(d, A, B, sbase, m0, n0, tid);

    const int lane = tid & 31, wid = tid >> 5, wm = wid & 3, wn = wid >> 2;
#pragma unroll
    for (int mt = 0; mt < 2; mt++) {
        const int row0 = m0 + wm * 32 + mt * 16 + (lane >> 2);
#pragma unroll
        for (int nt = 0; nt < 8; nt++) {
            const int col = n0 + wn * 64 + nt * 8 + (lane & 3) * 2;
            const float bx = bias[col], by = bias[col + 1];
            *(float2*)(Cf + (size_t)row0 * 1024 + col) =
                make_float2(d[mt][nt][0] + bx, d[mt][nt][1] + by);
            *(float2*)(Cf + (size_t)(row0 + 8) * 1024 + col) =
                make_float2(d[mt][nt][2] + bx, d[mt][nt][3] + by);
        }
    }
}

// ============================ tensor-core banded attention ============================
// R9 inner body; 128-key staging (2 stages), one sync per 128 keys.
// SAFE ordering: wait -> syncthreads -> issue next stage (fixes R12 WAR race).
#define AQS     72
#define A_Q     0                         // 128*72 = 9216 elems
#define A_KV    9216
#define A_TILE2 (128 * AQS)               // 9216 elems (K or V, 128 keys)
#define A_STAGE2 (2 * A_TILE2)            // 18432
#define ATTN_SMEM ((A_KV + 2 * A_STAGE2) * 2)   // 92160 B -> 2 CTAs/SM

__global__ __launch_bounds__(256, 2)
void attn_mma_kernel(const __half* __restrict__ q,
                     const __half* __restrict__ k16,
                     const __half* __restrict__ v16,
                     __half* __restrict__ o) {
    extern __shared__ char smem[];
    const uint32_t sbase = smem_u32(smem);
    const int tid = threadIdx.x, lane = tid & 31, w = tid >> 5;
    const int qt = blockIdx.x, h = blockIdx.y, b = blockIdx.z;
    const int qi0 = qt * 128;

    int u_start = 0;
    { int lim = qi0 - 1153; if (lim > 0) u_start = ((lim + 127) >> 7) << 7; }   // 128-aligned

    // Q load (group 0)
    {
#pragma unroll
        for (int it = 0; it < 4; it++) {
            int cid = tid + it * 256;
            int r = cid >> 3, qq = cid & 7;
            const void* src = q + ((size_t)(b * 2048 + qi0 + r) << 10) + h * 64 + qq * 8;
            uint32_t dst = sbase + (uint32_t)((A_Q + r * AQS + qq * 8) * 2);
            cp_async16(dst, src);
        }
        cp_commit();
    }

    // 128-key K+V stage load: 2 tiles x 128 rows x 8 chunks = 2048 -> 8/thread
    auto issue_kv = [&](int u0, int s) {
#pragma unroll
        for (int it = 0; it < 8; it++) {
            int cid = tid + it * 256;
            int t = cid >> 10, r = (cid >> 3) & 127, qq = cid & 7;
            const __half* bp = t ? v16 : k16;
            const void* src = bp + ((size_t)(b * 1024 + u0 + r) << 10) + h * 64 + qq * 8;
            uint32_t dst = sbase + (uint32_t)((A_KV + s * A_STAGE2 + t * A_TILE2
                                               + r * AQS + qq * 8) * 2);
            cp_async16(dst, src);
        }
        cp_commit();
    };
    issue_kv(u_start, 0);

    float d[8][4];
#pragma unroll
    for (int nt = 0; nt < 8; nt++)
#pragma unroll
        for (int e = 0; e < 4; e++) d[nt][e] = 0.0f;
    float dl[4] = {0.0f, 0.0f, 0.0f, 0.0f};

    const int i0 = qi0 + w * 16 + (lane >> 2);
    const int i1 = i0 + 8;
    const uint32_t ONES2 = 0x3C003C00u;

    const int nIter = (1024 - u_start) >> 7;
    for (int itn = 0; itn < nIter; itn++) {
        const int ub = u_start + itn * 128;
        const int s  = itn & 1;

        // current stage resident (only this stage's group + maybe Q pending)
        asm volatile("cp.async.wait_group 0;" ::: "memory");
        __syncthreads();                 // all warps done reading stage s^1 (prev iter)
        if (itn + 1 < nIter) issue_kv(ub + 128, s ^ 1);   // safe overwrite; overlaps compute

        const uint32_t stg = sbase + (uint32_t)((A_KV + s * A_STAGE2) * 2);

#pragma unroll
        for (int half = 0; half < 2; half++) {
            const int u0 = ub + half * 64;
            const uint32_t koff = stg + (uint32_t)(half * 64 * AQS * 2);
            const uint32_t vbase = stg + (uint32_t)(A_TILE2 * 2) + (uint32_t)(half * 64 * AQS * 2);

            // ---- S = Q * K ----
            float s_[8][4];
#pragma unroll
            for (int nt = 0; nt < 8; nt++)
#pragma unroll
                for (int e = 0; e < 4; e++) s_[nt][e] = 0.0f;

#pragma unroll
            for (int ks = 0; ks < 4; ks++) {
                uint32_t af[4];
                ldsm_x4(af[0], af[1], af[2], af[3],
                    sbase + (uint32_t)(((w * 16 + (lane & 15)) * AQS + ks * 16 + (lane >> 4) * 8) * 2));
                const int mrow = lane >> 3;
                uint32_t bf[4][4];
#pragma unroll
                for (int g = 0; g < 4; g++)
                    ldsm_x4(bf[g][0], bf[g][1], bf[g][2], bf[g][3],
                        koff + (uint32_t)(((g * 16 + (mrow & 2) * 4 + (lane & 7)) * AQS
                                          + ks * 16 + (mrow & 1) * 8) * 2));
#pragma unroll
                for (int nt = 0; nt < 8; nt++)
                    mma_f16(s_[nt], af, bf[nt >> 1][(nt & 1) * 2], bf[nt >> 1][(nt & 1) * 2 + 1]);
            }

            // ---- p = exp2(s) packed to half2 (no running max; bias folds mf) ----
            const bool t1_all  = (u0 >= qi0 + 125);
            const bool t1_none = (u0 < qi0 - 65);
            const bool t2_all  = (u0 >= qi0 - 899);
            const bool uniform = (t1_all || t1_none) && t2_all;

            uint32_t ph2[8][2];
            if (uniform) {
                const __half2 bias2 = __float2half2_rn(t1_all ? 1.0f : 0.0f);
#pragma unroll
                for (int nt = 0; nt < 8; nt++) {
                    __half2 a0 = h2exp2(__hadd2(__floats2half2_rn(s_[nt][0], s_[nt][1]), bias2));
                    __half2 a1 = h2exp2(__hadd2(__floats2half2_rn(s_[nt][2], s_[nt][3]), bias2));
                    ph2[nt][0] = *reinterpret_cast<uint32_t*>(&a0);
                    ph2[nt][1] = *reinterpret_cast<uint32_t*>(&a1);
                }
            } else {
#pragma unroll
                for (int nt = 0; nt < 8; nt++) {
                    const int uc = u0 + nt * 8 + (lane & 3) * 2;
                    float sv[4];
#pragma unroll
                    for (int e = 0; e < 4; e++) {
                        const int u = uc + (e & 1);
                        const int i = (e < 2) ? i0 : i1;
                        const int mf = (u >= i - 2) + (u >= i - 1026);
                        sv[e] = (mf == 0) ? -1000.0f : s_[nt][e] + (mf == 2 ? 1.0f : 0.0f);
                    }
                    __half2 a0 = h2exp2(__floats2half2_rn(sv[0], sv[1]));
                    __half2 a1 = h2exp2(__floats2half2_rn(sv[2], sv[3]));
                    ph2[nt][0] = *reinterpret_cast<uint32_t*>(&a0);
                    ph2[nt][1] = *reinterpret_cast<uint32_t*>(&a1);
                }
            }

            // ---- O += P * V ; l += P * ones ----
#pragma unroll
            for (int ks = 0; ks < 4; ks++) {
                uint32_t ph[4];
                ph[0] = ph2[2 * ks][0];
                ph[1] = ph2[2 * ks][1];
                ph[2] = ph2[2 * ks + 1][0];
                ph[3] = ph2[2 * ks + 1][1];
                mma_f16(dl, ph, ONES2, ONES2);

                const uint32_t voff = (uint32_t)(((ks * 16 + ((lane >> 3) & 1) * 8 + (lane & 7)) * AQS) * 2)
                                    + (uint32_t)((lane >> 4) * 16);
#pragma unroll
                for (int t = 0; t < 4; t++) {
                    uint32_t vf[4];
                    ldsm_x4_t(vf[0], vf[1], vf[2], vf[3],
                              vbase + voff + (uint32_t)(t * 32));
                    mma_f16(d[2 * t + 0], ph, vf[0], vf[1]);
                    mma_f16(d[2 * t + 1], ph, vf[2], vf[3]);
                }
            }
        }
    }

    // ---- epilogue ----
    const float inv0 = 1.0f / dl[0], inv1 = 1.0f / dl[2];
    const size_t row0 = (size_t)(b * 2048 + qi0 + w * 16 + (lane >> 2));
#pragma unroll
    for (int nt = 0; nt < 8; nt++) {
        const int col = h * 64 + nt * 8 + (lane & 3) * 2;
        *(__half2*)(o + row0 * 1024 + col)       = __floats2half2_rn(d[nt][0] * inv0, d[nt][1] * inv0);
        *(__half2*)(o + (row0 + 8) * 1024 + col) = __floats2half2_rn(d[nt][2] * inv1, d[nt][3] * inv1);
    }
}

// ============================ launch ============================
extern "C" void kernel_launch(void* const* d_in, const int* in_sizes, int n_in,
                              void* d_out, int out_size) {
    const float* x  = (const float*)d_in[0];
    const float* xd = (const float*)d_in[1];
    const float* Wq = (const float*)d_in[2];
    const float* Wk = (const float*)d_in[3];
    const float* Wv = (const float*)d_in[4];
    const float* Wo = (const float*)d_in[5];
    const float* bo = (const float*)d_in[6];
    float* out = (float*)d_out;

    __half *x16, *d16, *q16, *k16, *v16, *ao, *wq, *wk, *wv, *wo;
    cudaGetSymbolAddress((void**)&x16, g_x16);  cudaGetSymbolAddress((void**)&d16, g_d16);
    cudaGetSymbolAddress((void**)&q16, g_q16);  cudaGetSymbolAddress((void**)&k16, g_k16);
    cudaGetSymbolAddress((void**)&v16, g_v16);  cudaGetSymbolAddress((void**)&ao,  g_ao);
    cudaGetSymbolAddress((void**)&wq,  g_wq);   cudaGetSymbolAddress((void**)&wk,  g_wk);
    cudaGetSymbolAddress((void**)&wv,  g_wv);   cudaGetSymbolAddress((void**)&wo,  g_wo);

    cudaFuncSetAttribute(gemm_qkv_kernel, cudaFuncAttributeMaxDynamicSharedMemorySize, G_SMEM);
    cudaFuncSetAttribute(gemm_o_kernel,   cudaFuncAttributeMaxDynamicSharedMemorySize, G_SMEM);
    cudaFuncSetAttribute(attn_mma_kernel, cudaFuncAttributeMaxDynamicSharedMemorySize, ATTN_SMEM);

    const float qscale = 0.125f * 1.44269504088896341f;

    prep_kernel<<<NCAST + 4096, 256>>>(x, xd, Wq, Wk, Wv, Wo, x16, d16, wq, wk, wv, wo);

    gemm_qkv_kernel<<<dim3(8, 64), 256, G_SMEM>>>(x16, d16, wq, wk, wv, q16, k16, v16, qscale);

    attn_mma_kernel<<<dim3(16, 16, 2), 256, ATTN_SMEM>>>(q16, k16, v16, ao);

    gemm_o_kernel<<<dim3(8, 32), 256, G_SMEM>>>(ao, wo, out, bo);
}

// round 14
// speedup vs baseline: 1.0313x; 1.0046x over previous
#include <cuda_runtime.h>
#include <cuda_fp16.h>
#include <cstdint>

// ============================ scratch (allocation-free) ============================
__device__ __half g_x16[4096 * 1024];
__device__ __half g_d16[2048 * 1024];
__device__ __half g_q16[4096 * 1024];
__device__ __half g_k16[2048 * 1024];
__device__ __half g_v16[2048 * 1024];
__device__ __half g_ao [4096 * 1024];
__device__ __half g_wq [1024 * 1024];
__device__ __half g_wk [1024 * 1024];
__device__ __half g_wv [1024 * 1024];
__device__ __half g_wo [1024 * 1024];

// ============================ PTX helpers (arch-generic) ============================
__device__ __forceinline__ uint32_t smem_u32(const void* p) {
    uint32_t a;
    asm("{ .reg .u64 t; cvta.to.shared.u64 t, %1; cvt.u32.u64 %0, t; }" : "=r"(a) : "l"(p));
    return a;
}
__device__ __forceinline__ void ldsm_x4(uint32_t& r0, uint32_t& r1, uint32_t& r2, uint32_t& r3,
                                        uint32_t addr) {
    asm volatile("ldmatrix.sync.aligned.m8n8.x4.shared.b16 {%0,%1,%2,%3}, [%4];"
                 : "=r"(r0), "=r"(r1), "=r"(r2), "=r"(r3) : "r"(addr));
}
__device__ __forceinline__ void ldsm_x4_t(uint32_t& r0, uint32_t& r1, uint32_t& r2, uint32_t& r3,
                                          uint32_t addr) {
    asm volatile("ldmatrix.sync.aligned.m8n8.x4.trans.shared.b16 {%0,%1,%2,%3}, [%4];"
                 : "=r"(r0), "=r"(r1), "=r"(r2), "=r"(r3) : "r"(addr));
}
__device__ __forceinline__ void mma_f16(float* d, const uint32_t* a, uint32_t b0, uint32_t b1) {
    asm volatile("mma.sync.aligned.m16n8k16.row.col.f32.f16.f16.f32 "
                 "{%0,%1,%2,%3}, {%4,%5,%6,%7}, {%8,%9}, {%0,%1,%2,%3};"
                 : "+f"(d[0]), "+f"(d[1]), "+f"(d[2]), "+f"(d[3])
                 : "r"(a[0]), "r"(a[1]), "r"(a[2]), "r"(a[3]), "r"(b0), "r"(b1));
}
__device__ __forceinline__ void cp_async16(uint32_t dst, const void* src) {
    asm volatile("cp.async.cg.shared.global [%0], [%1], 16;" :: "r"(dst), "l"(src) : "memory");
}
__device__ __forceinline__ void cp_commit() {
    asm volatile("cp.async.commit_group;" ::: "memory");
}

// ============================ fused conversion (one launch) ============================
#define NX4 (4096 * 1024 / 4)
#define ND4 (2048 * 1024 / 4)
#define NCAST ((NX4 + ND4) / 256)          // 6144 blocks for casting
__global__ void prep_kernel(const float* __restrict__ x, const float* __restrict__ xd,
                            const float* __restrict__ W0, const float* __restrict__ W1,
                            const float* __restrict__ W2, const float* __restrict__ W3,
                            __half* __restrict__ x16, __half* __restrict__ d16,
                            __half* __restrict__ T0, __half* __restrict__ T1,
                            __half* __restrict__ T2, __half* __restrict__ T3,
                            float w0scale) {
    const int bx = blockIdx.x;
    const int tid = threadIdx.x;
    if (bx < NCAST) {
        int i = bx * 256 + tid;
        const float* in; __half* out; int j;
        if (i < NX4) { in = x;  out = x16; j = i; }
        else         { in = xd; out = d16; j = i - NX4; }
        float4 v = ((const float4*)in)[j];
        ((__half2*)out)[2 * j + 0] = __floats2half2_rn(v.x, v.y);
        ((__half2*)out)[2 * j + 1] = __floats2half2_rn(v.z, v.w);
        return;
    }
    // weight transpose: idx decodes (z, by, bx32); Wq (z==0) pre-scaled by w0scale
    const int idx = bx - NCAST;                 // 0..4095
    const int z   = idx >> 10;
    const int byy = (idx >> 5) & 31;
    const int bxx = idx & 31;
    const float* W = (z == 0) ? W0 : (z == 1) ? W1 : (z == 2) ? W2 : W3;
    __half* T = (z == 0) ? T0 : (z == 1) ? T1 : (z == 2) ? T2 : T3;
    const float sc = (z == 0) ? w0scale : 1.0f;
    const int tx = tid & 31, ty = tid >> 5;     // 32 x 8
    __shared__ float t[32][33];
    int xcol = bxx * 32 + tx;
#pragma unroll
    for (int j = 0; j < 32; j += 8) {
        int kk = byy * 32 + ty + j;
        t[ty + j][tx] = W[kk * 1024 + xcol];
    }
    __syncthreads();
    int kx = byy * 32 + tx;
#pragma unroll
    for (int j = 0; j < 32; j += 8) {
        int n = bxx * 32 + ty + j;
        T[n * 1024 + kx] = __float2half_rn(t[tx][ty + j] * sc);
    }
}

// ============================ fp16 1-term GEMM core (R9: 128x128, 3-stage) ============
#define GTS      72
#define GTILE_B  (128 * GTS * 2)        // 18432
#define G_SMEM   (6 * GTILE_B)          // 110592

struct GemmCore {
    __device__ static void run(float d[2][8][4], const __half* A, const __half* B,
                               uint32_t sbase, int m0, int n0, int tid) {
        const int lane = tid & 31;
        const int wid  = tid >> 5;
        const int wm   = wid & 3;
        const int wn   = wid >> 2;

        auto issue_loads = [&](int c, int s) {
#pragma unroll
            for (int it = 0; it < 8; it++) {
                const int part = it >> 2;               // 0=A, 1=B
                const int w    = tid + (it & 3) * 256;
                const int row  = w >> 3;
                const int q    = w & 7;
                const __half* base = part ? B : A;
                const int grow = part ? (n0 + row) : (m0 + row);
                const void* src = base + ((size_t)grow << 10) + c * 64 + q * 8;
                uint32_t dst = sbase + (uint32_t)((s * 2 + part) * GTILE_B)
                             + (uint32_t)((row * GTS + q * 8) * 2);
                cp_async16(dst, src);
            }
            cp_commit();
        };

#pragma unroll
        for (int mt = 0; mt < 2; mt++)
#pragma unroll
            for (int nt = 0; nt < 8; nt++)
#pragma unroll
                for (int e = 0; e < 4; e++) d[mt][nt][e] = 0.0f;

        issue_loads(0, 0);
        issue_loads(1, 1);

        int ld_stage = 2, cur = 0;
        for (int c = 0; c < 16; c++) {
            asm volatile("cp.async.wait_group 1;" ::: "memory");
            __syncthreads();
            if (c + 2 < 16) issue_loads(c + 2, ld_stage);
            else            cp_commit();
            ld_stage = (ld_stage == 2) ? 0 : ld_stage + 1;

            const uint32_t stage = sbase + (uint32_t)(cur * 2 * GTILE_B);
            cur = (cur == 2) ? 0 : cur + 1;
            const uint32_t bbase = stage + (uint32_t)GTILE_B;
#pragma unroll
            for (int ks = 0; ks < 4; ks++) {
                const int k16 = ks * 16;
                uint32_t af[2][4];
#pragma unroll
                for (int mt = 0; mt < 2; mt++) {
                    uint32_t addr = stage +
                        (uint32_t)(((wm * 32 + mt * 16 + (lane & 15)) * GTS
                                    + k16 + ((lane >> 4) * 8)) * 2);
                    ldsm_x4(af[mt][0], af[mt][1], af[mt][2], af[mt][3], addr);
                }
                const int mrow = lane >> 3;
                uint32_t bf[4][4];
#pragma unroll
                for (int g = 0; g < 4; g++) {
                    uint32_t addr = bbase +
                        (uint32_t)(((wn * 64 + g * 16 + (mrow & 2) * 4 + (lane & 7)) * GTS
                                    + k16 + ((mrow & 1) * 8)) * 2);
                    ldsm_x4(bf[g][0], bf[g][1], bf[g][2], bf[g][3], addr);
                }
#pragma unroll
                for (int mt = 0; mt < 2; mt++)
#pragma unroll
                    for (int nt = 0; nt < 8; nt++)
                        mma_f16(d[mt][nt], af[mt],
                                bf[nt >> 1][(nt & 1) * 2], bf[nt >> 1][(nt & 1) * 2 + 1]);
            }
        }
    }
};

// merged q/k/v projection: grid (8, 64); by<32: q, by<48: k, else v. fp16 out.
// qscale is folded into wq at prep time -> no alpha path.
__global__ __launch_bounds__(256, 2)
void gemm_qkv_kernel(const __half* __restrict__ x16, const __half* __restrict__ d16,
                     const __half* __restrict__ wq, const __half* __restrict__ wk,
                     const __half* __restrict__ wv,
                     __half* __restrict__ q16, __half* __restrict__ k16,
                     __half* __restrict__ v16) {
    extern __shared__ char smem[];
    const uint32_t sbase = smem_u32(smem);
    const int tid = threadIdx.x;
    const int by  = blockIdx.y;

    const __half* A; const __half* B; __half* C; int m0;
    if (by < 32)      { A = x16; B = wq; C = q16; m0 = by * 128; }
    else if (by < 48) { A = d16; B = wk; C = k16; m0 = (by - 32) * 128; }
    else              { A = d16; B = wv; C = v16; m0 = (by - 48) * 128; }
    const int n0 = blockIdx.x * 128;

    float d[2][8][4];
    GemmCore::run(d, A, B, sbase, m0, n0, tid);

    const int lane = tid & 31, wid = tid >> 5, wm = wid & 3, wn = wid >> 2;
#pragma unroll
    for (int mt = 0; mt < 2; mt++) {
        const int row0 = m0 + wm * 32 + mt * 16 + (lane >> 2);
#pragma unroll
        for (int nt = 0; nt < 8; nt++) {
            const int col = n0 + wn * 64 + nt * 8 + (lane & 3) * 2;
            *(__half2*)(C + (size_t)row0 * 1024 + col) =
                __floats2half2_rn(d[mt][nt][0], d[mt][nt][1]);
            *(__half2*)(C + (size_t)(row0 + 8) * 1024 + col) =
                __floats2half2_rn(d[mt][nt][2], d[mt][nt][3]);
        }
    }
}

// output projection: fp32 + bias
__global__ __launch_bounds__(256, 2)
void gemm_o_kernel(const __half* __restrict__ A, const __half* __restrict__ B,
                   float* __restrict__ Cf, const float* __restrict__ bias) {
    extern __shared__ char smem[];
    const uint32_t sbase = smem_u32(smem);
    const int tid = threadIdx.x;
    const int m0 = blockIdx.y * 128;
    const int n0 = blockIdx.x * 128;

    float d[2][8][4];
    GemmCore::run(d, A, B, sbase, m0, n0, tid);

    const int lane = tid & 31, wid = tid >> 5, wm = wid & 3, wn = wid >> 2;
#pragma unroll
    for (int mt = 0; mt < 2; mt++) {
        const int row0 = m0 + wm * 32 + mt * 16 + (lane >> 2);
#pragma unroll
        for (int nt = 0; nt < 8; nt++) {
            const int col = n0 + wn * 64 + nt * 8 + (lane & 3) * 2;
            const float bx = bias[col], by = bias[col + 1];
            *(float2*)(Cf + (size_t)row0 * 1024 + col) =
                make_float2(d[mt][nt][0] + bx, d[mt][nt][1] + by);
            *(float2*)(Cf + (size_t)(row0 + 8) * 1024 + col) =
                make_float2(d[mt][nt][2] + bx, d[mt][nt][3] + by);
        }
    }
}

// ============================ tensor-core banded attention ============================
// R13 structure: 128-key staging (2 stages), safe wait->sync->issue ordering,
// plus a 64-granularity skip of fully-masked first halves.
#define AQS     72
#define A_Q     0                         // 128*72 = 9216 elems
#define A_KV    9216
#define A_TILE2 (128 * AQS)               // 9216 elems (K or V, 128 keys)
#define A_STAGE2 (2 * A_TILE2)            // 18432
#define ATTN_SMEM ((A_KV + 2 * A_STAGE2) * 2)   // 92160 B -> 2 CTAs/SM

__global__ __launch_bounds__(256, 2)
void attn_mma_kernel(const __half* __restrict__ q,
                     const __half* __restrict__ k16,
                     const __half* __restrict__ v16,
                     __half* __restrict__ o) {
    extern __shared__ char smem[];
    const uint32_t sbase = smem_u32(smem);
    const int tid = threadIdx.x, lane = tid & 31, w = tid >> 5;
    const int qt = blockIdx.x, h = blockIdx.y, b = blockIdx.z;
    const int qi0 = qt * 128;

    int u_start = 0;
    { int lim = qi0 - 1153; if (lim > 0) u_start = ((lim + 127) >> 7) << 7; }   // 128-aligned

    // Q load (group 0)
    {
#pragma unroll
        for (int it = 0; it < 4; it++) {
            int cid = tid + it * 256;
            int r = cid >> 3, qq = cid & 7;
            const void* src = q + ((size_t)(b * 2048 + qi0 + r) << 10) + h * 64 + qq * 8;
            uint32_t dst = sbase + (uint32_t)((A_Q + r * AQS + qq * 8) * 2);
            cp_async16(dst, src);
        }
        cp_commit();
    }

    // 128-key K+V stage load: 2 tiles x 128 rows x 8 chunks = 2048 -> 8/thread
    auto issue_kv = [&](int u0, int s) {
#pragma unroll
        for (int it = 0; it < 8; it++) {
            int cid = tid + it * 256;
            int t = cid >> 10, r = (cid >> 3) & 127, qq = cid & 7;
            const __half* bp = t ? v16 : k16;
            const void* src = bp + ((size_t)(b * 1024 + u0 + r) << 10) + h * 64 + qq * 8;
            uint32_t dst = sbase + (uint32_t)((A_KV + s * A_STAGE2 + t * A_TILE2
                                               + r * AQS + qq * 8) * 2);
            cp_async16(dst, src);
        }
        cp_commit();
    };
    issue_kv(u_start, 0);

    float d[8][4];
#pragma unroll
    for (int nt = 0; nt < 8; nt++)
#pragma unroll
        for (int e = 0; e < 4; e++) d[nt][e] = 0.0f;
    float dl[4] = {0.0f, 0.0f, 0.0f, 0.0f};

    const int i0 = qi0 + w * 16 + (lane >> 2);
    const int i1 = i0 + 8;
    const uint32_t ONES2 = 0x3C003C00u;

    const int nIter = (1024 - u_start) >> 7;
    for (int itn = 0; itn < nIter; itn++) {
        const int ub = u_start + itn * 128;
        const int s  = itn & 1;

        asm volatile("cp.async.wait_group 0;" ::: "memory");
        __syncthreads();                 // all warps done reading stage s^1 (prev iter)
        if (itn + 1 < nIter) issue_kv(ub + 128, s ^ 1);   // safe overwrite; overlaps compute

        const uint32_t stg = sbase + (uint32_t)((A_KV + s * A_STAGE2) * 2);

#pragma unroll
        for (int half = 0; half < 2; half++) {
            const int u0 = ub + half * 64;
            if (u0 + 63 < qi0 - 1026) continue;   // fully-masked 64-half (block-uniform)
            const uint32_t koff = stg + (uint32_t)(half * 64 * AQS * 2);
            const uint32_t vbase = stg + (uint32_t)(A_TILE2 * 2) + (uint32_t)(half * 64 * AQS * 2);

            // ---- S = Q * K ----
            float s_[8][4];
#pragma unroll
            for (int nt = 0; nt < 8; nt++)
#pragma unroll
                for (int e = 0; e < 4; e++) s_[nt][e] = 0.0f;

#pragma unroll
            for (int ks = 0; ks < 4; ks++) {
                uint32_t af[4];
                ldsm_x4(af[0], af[1], af[2], af[3],
                    sbase + (uint32_t)(((w * 16 + (lane & 15)) * AQS + ks * 16 + (lane >> 4) * 8) * 2));
                const int mrow = lane >> 3;
                uint32_t bf[4][4];
#pragma unroll
                for (int g = 0; g < 4; g++)
                    ldsm_x4(bf[g][0], bf[g][1], bf[g][2], bf[g][3],
                        koff + (uint32_t)(((g * 16 + (mrow & 2) * 4 + (lane & 7)) * AQS
                                          + ks * 16 + (mrow & 1) * 8) * 2));
#pragma unroll
                for (int nt = 0; nt < 8; nt++)
                    mma_f16(s_[nt], af, bf[nt >> 1][(nt & 1) * 2], bf[nt >> 1][(nt & 1) * 2 + 1]);
            }

            // ---- p = exp2(s) packed to half2 (no running max; bias folds mf) ----
            const bool t1_all  = (u0 >= qi0 + 125);
            const bool t1_none = (u0 < qi0 - 65);
            const bool t2_all  = (u0 >= qi0 - 899);
            const bool uniform = (t1_all || t1_none) && t2_all;

            uint32_t ph2[8][2];
            if (uniform) {
                const __half2 bias2 = __float2half2_rn(t1_all ? 1.0f : 0.0f);
#pragma unroll
                for (int nt = 0; nt < 8; nt++) {
                    __half2 a0 = h2exp2(__hadd2(__floats2half2_rn(s_[nt][0], s_[nt][1]), bias2));
                    __half2 a1 = h2exp2(__hadd2(__floats2half2_rn(s_[nt][2], s_[nt][3]), bias2));
                    ph2[nt][0] = *reinterpret_cast<uint32_t*>(&a0);
                    ph2[nt][1] = *reinterpret_cast<uint32_t*>(&a1);
                }
            } else {
#pragma unroll
                for (int nt = 0; nt < 8; nt++) {
                    const int uc = u0 + nt * 8 + (lane & 3) * 2;
                    float sv[4];
#pragma unroll
                    for (int e = 0; e < 4; e++) {
                        const int u = uc + (e & 1);
                        const int i = (e < 2) ? i0 : i1;
                        const int mf = (u >= i - 2) + (u >= i - 1026);
                        sv[e] = (mf == 0) ? -1000.0f : s_[nt][e] + (mf == 2 ? 1.0f : 0.0f);
                    }
                    __half2 a0 = h2exp2(__floats2half2_rn(sv[0], sv[1]));
                    __half2 a1 = h2exp2(__floats2half2_rn(sv[2], sv[3]));
                    ph2[nt][0] = *reinterpret_cast<uint32_t*>(&a0);
                    ph2[nt][1] = *reinterpret_cast<uint32_t*>(&a1);
                }
            }

            // ---- O += P * V ; l += P * ones ----
#pragma unroll
            for (int ks = 0; ks < 4; ks++) {
                uint32_t ph[4];
                ph[0] = ph2[2 * ks][0];
                ph[1] = ph2[2 * ks][1];
                ph[2] = ph2[2 * ks + 1][0];
                ph[3] = ph2[2 * ks + 1][1];
                mma_f16(dl, ph, ONES2, ONES2);

                const uint32_t voff = (uint32_t)(((ks * 16 + ((lane >> 3) & 1) * 8 + (lane & 7)) * AQS) * 2)
                                    + (uint32_t)((lane >> 4) * 16);
#pragma unroll
                for (int t = 0; t < 4; t++) {
                    uint32_t vf[4];
                    ldsm_x4_t(vf[0], vf[1], vf[2], vf[3],
                              vbase + voff + (uint32_t)(t * 32));
                    mma_f16(d[2 * t + 0], ph, vf[0], vf[1]);
                    mma_f16(d[2 * t + 1], ph, vf[2], vf[3]);
                }
            }
        }
    }

    // ---- epilogue ----
    const float inv0 = 1.0f / dl[0], inv1 = 1.0f / dl[2];
    const size_t row0 = (size_t)(b * 2048 + qi0 + w * 16 + (lane >> 2));
#pragma unroll
    for (int nt = 0; nt < 8; nt++) {
        const int col = h * 64 + nt * 8 + (lane & 3) * 2;
        *(__half2*)(o + row0 * 1024 + col)       = __floats2half2_rn(d[nt][0] * inv0, d[nt][1] * inv0);
        *(__half2*)(o + (row0 + 8) * 1024 + col) = __floats2half2_rn(d[nt][2] * inv1, d[nt][3] * inv1);
    }
}

// ============================ launch ============================
extern "C" void kernel_launch(void* const* d_in, const int* in_sizes, int n_in,
                              void* d_out, int out_size) {
    const float* x  = (const float*)d_in[0];
    const float* xd = (const float*)d_in[1];
    const float* Wq = (const float*)d_in[2];
    const float* Wk = (const float*)d_in[3];
    const float* Wv = (const float*)d_in[4];
    const float* Wo = (const float*)d_in[5];
    const float* bo = (const float*)d_in[6];
    float* out = (float*)d_out;

    __half *x16, *d16, *q16, *k16, *v16, *ao, *wq, *wk, *wv, *wo;
    cudaGetSymbolAddress((void**)&x16, g_x16);  cudaGetSymbolAddress((void**)&d16, g_d16);
    cudaGetSymbolAddress((void**)&q16, g_q16);  cudaGetSymbolAddress((void**)&k16, g_k16);
    cudaGetSymbolAddress((void**)&v16, g_v16);  cudaGetSymbolAddress((void**)&ao,  g_ao);
    cudaGetSymbolAddress((void**)&wq,  g_wq);   cudaGetSymbolAddress((void**)&wk,  g_wk);
    cudaGetSymbolAddress((void**)&wv,  g_wv);   cudaGetSymbolAddress((void**)&wo,  g_wo);

    cudaFuncSetAttribute(gemm_qkv_kernel, cudaFuncAttributeMaxDynamicSharedMemorySize, G_SMEM);
    cudaFuncSetAttribute(gemm_o_kernel,   cudaFuncAttributeMaxDynamicSharedMemorySize, G_SMEM);
    cudaFuncSetAttribute(attn_mma_kernel, cudaFuncAttributeMaxDynamicSharedMemorySize, ATTN_SMEM);

    const float qscale = 0.125f * 1.44269504088896341f;

    prep_kernel<<<NCAST + 4096, 256>>>(x, xd, Wq, Wk, Wv, Wo,
                                       x16, d16, wq, wk, wv, wo, qscale);

    gemm_qkv_kernel<<<dim3(8, 64), 256, G_SMEM>>>(x16, d16, wq, wk, wv, q16, k16, v16);

    attn_mma_kernel<<<dim3(16, 16, 2), 256, ATTN_SMEM>>>(q16, k16, v16, ao);

    gemm_o_kernel<<<dim3(8, 32), 256, G_SMEM>>>(ao, wo, out, bo);
}

// round 15
// speedup vs baseline: 1.0496x; 1.0177x over previous
#include <cuda_runtime.h>
#include <cuda_fp16.h>
#include <cstdint>

// ============================ scratch (allocation-free) ============================
__device__ __half g_x16[4096 * 1024];
__device__ __half g_d16[2048 * 1024];
__device__ __half g_q16[4096 * 1024];
__device__ __half g_k16[2048 * 1024];
__device__ __half g_v16[2048 * 1024];
__device__ __half g_ao [4096 * 1024];
__device__ __half g_wq [1024 * 1024];   // natural [k][n] layout, fp16 (Wq pre-scaled)
__device__ __half g_wk [1024 * 1024];
__device__ __half g_wv [1024 * 1024];
__device__ __half g_wo [1024 * 1024];

// ============================ PTX helpers (arch-generic) ============================
__device__ __forceinline__ uint32_t smem_u32(const void* p) {
    uint32_t a;
    asm("{ .reg .u64 t; cvta.to.shared.u64 t, %1; cvt.u32.u64 %0, t; }" : "=r"(a) : "l"(p));
    return a;
}
__device__ __forceinline__ void ldsm_x4(uint32_t& r0, uint32_t& r1, uint32_t& r2, uint32_t& r3,
                                        uint32_t addr) {
    asm volatile("ldmatrix.sync.aligned.m8n8.x4.shared.b16 {%0,%1,%2,%3}, [%4];"
                 : "=r"(r0), "=r"(r1), "=r"(r2), "=r"(r3) : "r"(addr));
}
__device__ __forceinline__ void ldsm_x4_t(uint32_t& r0, uint32_t& r1, uint32_t& r2, uint32_t& r3,
                                          uint32_t addr) {
    asm volatile("ldmatrix.sync.aligned.m8n8.x4.trans.shared.b16 {%0,%1,%2,%3}, [%4];"
                 : "=r"(r0), "=r"(r1), "=r"(r2), "=r"(r3) : "r"(addr));
}
__device__ __forceinline__ void mma_f16(float* d, const uint32_t* a, uint32_t b0, uint32_t b1) {
    asm volatile("mma.sync.aligned.m16n8k16.row.col.f32.f16.f16.f32 "
                 "{%0,%1,%2,%3}, {%4,%5,%6,%7}, {%8,%9}, {%0,%1,%2,%3};"
                 : "+f"(d[0]), "+f"(d[1]), "+f"(d[2]), "+f"(d[3])
                 : "r"(a[0]), "r"(a[1]), "r"(a[2]), "r"(a[3]), "r"(b0), "r"(b1));
}
__device__ __forceinline__ void cp_async16(uint32_t dst, const void* src) {
    asm volatile("cp.async.cg.shared.global [%0], [%1], 16;" :: "r"(dst), "l"(src) : "memory");
}
__device__ __forceinline__ void cp_commit() {
    asm volatile("cp.async.commit_group;" ::: "memory");
}

// ============================ prep: pure casts (no transpose) ============================
#define NX4 (4096 * 1024 / 4)
#define ND4 (2048 * 1024 / 4)
#define NW4 (1024 * 1024 / 4)             // 262144 float4 per weight
#define NPREP (NX4 + ND4 + 4 * NW4)       // 2621440 float4 total
__global__ void prep_kernel(const float* __restrict__ x, const float* __restrict__ xd,
                            const float* __restrict__ W0, const float* __restrict__ W1,
                            const float* __restrict__ W2, const float* __restrict__ W3,
                            __half* __restrict__ x16, __half* __restrict__ d16,
                            __half* __restrict__ T0, __half* __restrict__ T1,
                            __half* __restrict__ T2, __half* __restrict__ T3,
                            float w0scale) {
    int i = blockIdx.x * blockDim.x + threadIdx.x;
    if (i >= NPREP) return;
    const float* in; __half* out; int j; float sc = 1.0f;
    if (i < NX4)              { in = x;  out = x16; j = i; }
    else if (i < NX4 + ND4)   { in = xd; out = d16; j = i - NX4; }
    else {
        int wi = i - NX4 - ND4;
        int z  = wi >> 18;                // / NW4
        j      = wi & (NW4 - 1);
        in  = (z == 0) ? W0 : (z == 1) ? W1 : (z == 2) ? W2 : W3;
        out = (z == 0) ? T0 : (z == 1) ? T1 : (z == 2) ? T2 : T3;
        if (z == 0) sc = w0scale;
    }
    float4 v = ((const float4*)in)[j];
    ((__half2*)out)[2 * j + 0] = __floats2half2_rn(v.x * sc, v.y * sc);
    ((__half2*)out)[2 * j + 1] = __floats2half2_rn(v.z * sc, v.w * sc);
}

// ============================ fp16 1-term GEMM core ============================
// A [M,K] row-major fp16; B = W [K,N] row-major fp16 (consumed via ldsm.trans).
// 128x128 CTA tile, 3-stage cp.async pipeline, 1 sync/chunk.
#define GTS      72                        // A tile row stride (halves)
#define BTS      136                       // B tile row stride (halves): 272B, conflict-free
#define GA_B     (128 * GTS * 2)           // 18432
#define GB_B     (64 * BTS * 2)            // 17408
#define GSTAGE   (GA_B + GB_B)             // 35840
#define G_SMEM   (3 * GSTAGE)              // 107520 -> 2 CTAs/SM

struct GemmCore {
    __device__ static void run(float d[2][8][4], const __half* A, const __half* Bw,
                               uint32_t sbase, int m0, int n0, int tid) {
        const int lane = tid & 31;
        const int wid  = tid >> 5;
        const int wm   = wid & 3;
        const int wn   = wid >> 2;

        auto issue_loads = [&](int c, int s) {
            const uint32_t abase = sbase + (uint32_t)(s * GSTAGE);
            // A: 128 rows x 64 k (8 chunks/row)
#pragma unroll
            for (int it = 0; it < 4; it++) {
                const int cid = tid + it * 256;
                const int row = cid >> 3, q = cid & 7;
                const void* src = A + ((size_t)(m0 + row) << 10) + c * 64 + q * 8;
                cp_async16(abase + (uint32_t)((row * GTS + q * 8) * 2), src);
            }
            // B: 64 k-rows x 128 n (16 chunks/row), natural W[k][n]
            const uint32_t bb = abase + (uint32_t)GA_B;
#pragma unroll
            for (int it = 0; it < 4; it++) {
                const int cid = tid + it * 256;
                const int row = cid >> 4, q = cid & 15;
                const void* src = Bw + ((size_t)(c * 64 + row) << 10) + n0 + q * 8;
                cp_async16(bb + (uint32_t)((row * BTS + q * 8) * 2), src);
            }
            cp_commit();
        };

#pragma unroll
        for (int mt = 0; mt < 2; mt++)
#pragma unroll
            for (int nt = 0; nt < 8; nt++)
#pragma unroll
                for (int e = 0; e < 4; e++) d[mt][nt][e] = 0.0f;

        issue_loads(0, 0);
        issue_loads(1, 1);

        int ld_stage = 2, cur = 0;
        for (int c = 0; c < 16; c++) {
            asm volatile("cp.async.wait_group 1;" ::: "memory");
            __syncthreads();
            if (c + 2 < 16) issue_loads(c + 2, ld_stage);
            else            cp_commit();
            ld_stage = (ld_stage == 2) ? 0 : ld_stage + 1;

            const uint32_t stage = sbase + (uint32_t)(cur * GSTAGE);
            cur = (cur == 2) ? 0 : cur + 1;
            const uint32_t bb = stage + (uint32_t)GA_B;
            const uint32_t bcol = (uint32_t)((lane >> 4) * 16 + wn * 128);
#pragma unroll
            for (int ks = 0; ks < 4; ks++) {
                const int k16 = ks * 16;
                uint32_t af[2][4];
#pragma unroll
                for (int mt = 0; mt < 2; mt++) {
                    uint32_t addr = stage +
                        (uint32_t)(((wm * 32 + mt * 16 + (lane & 15)) * GTS
                                    + k16 + ((lane >> 4) * 8)) * 2);
                    ldsm_x4(af[mt][0], af[mt][1], af[mt][2], af[mt][3], addr);
                }
                // B fragments via trans ldsm (attn-V pattern): row = k, col = n
                const uint32_t brow = bb +
                    (uint32_t)(((k16 + ((lane >> 3) & 1) * 8 + (lane & 7)) * BTS) * 2) + bcol;
#pragma unroll
                for (int t = 0; t < 4; t++) {
                    uint32_t bf[4];
                    ldsm_x4_t(bf[0], bf[1], bf[2], bf[3], brow + (uint32_t)(t * 32));
#pragma unroll
                    for (int mt = 0; mt < 2; mt++) {
                        mma_f16(d[mt][2 * t + 0], af[mt], bf[0], bf[1]);
                        mma_f16(d[mt][2 * t + 1], af[mt], bf[2], bf[3]);
                    }
                }
            }
        }
    }
};

// merged q/k/v projection: grid (8, 64); by<32: q, by<48: k, else v. fp16 out.
__global__ __launch_bounds__(256, 2)
void gemm_qkv_kernel(const __half* __restrict__ x16, const __half* __restrict__ d16,
                     const __half* __restrict__ wq, const __half* __restrict__ wk,
                     const __half* __restrict__ wv,
                     __half* __restrict__ q16, __half* __restrict__ k16,
                     __half* __restrict__ v16) {
    extern __shared__ char smem[];
    const uint32_t sbase = smem_u32(smem);
    const int tid = threadIdx.x;
    const int by  = blockIdx.y;

    const __half* A; const __half* B; __half* C; int m0;
    if (by < 32)      { A = x16; B = wq; C = q16; m0 = by * 128; }
    else if (by < 48) { A = d16; B = wk; C = k16; m0 = (by - 32) * 128; }
    else              { A = d16; B = wv; C = v16; m0 = (by - 48) * 128; }
    const int n0 = blockIdx.x * 128;

    float d[2][8][4];
    GemmCore::run(d, A, B, sbase, m0, n0, tid);

    const int lane = tid & 31, wid = tid >> 5, wm = wid & 3, wn = wid >> 2;
#pragma unroll
    for (int mt = 0; mt < 2; mt++) {
        const int row0 = m0 + wm * 32 + mt * 16 + (lane >> 2);
#pragma unroll
        for (int nt = 0; nt < 8; nt++) {
            const int col = n0 + wn * 64 + nt * 8 + (lane & 3) * 2;
            *(__half2*)(C + (size_t)row0 * 1024 + col) =
                __floats2half2_rn(d[mt][nt][0], d[mt][nt][1]);
            *(__half2*)(C + (size_t)(row0 + 8) * 1024 + col) =
                __floats2half2_rn(d[mt][nt][2], d[mt][nt][3]);
        }
    }
}

// output projection: fp32 + bias
__global__ __launch_bounds__(256, 2)
void gemm_o_kernel(const __half* __restrict__ A, const __half* __restrict__ B,
                   float* __restrict__ Cf, const float* __restrict__ bias) {
    extern __shared__ char smem[];
    const uint32_t sbase = smem_u32(smem);
    const int tid = threadIdx.x;
    const int m0 = blockIdx.y * 128;
    const int n0 = blockIdx.x * 128;

    float d[2][8][4];
    GemmCore::run(d, A, B, sbase, m0, n0, tid);

    const int lane = tid & 31, wid = tid >> 5, wm = wid & 3, wn = wid >> 2;
#pragma unroll
    for (int mt = 0; mt < 2; mt++) {
        const int row0 = m0 + wm * 32 + mt * 16 + (lane >> 2);
#pragma unroll
        for (int nt = 0; nt < 8; nt++) {
            const int col = n0 + wn * 64 + nt * 8 + (lane & 3) * 2;
            const float bx = bias[col], by = bias[col + 1];
            *(float2*)(Cf + (size_t)row0 * 1024 + col) =
                make_float2(d[mt][nt][0] + bx, d[mt][nt][1] + by);
            *(float2*)(Cf + (size_t)(row0 + 8) * 1024 + col) =
                make_float2(d[mt][nt][2] + bx, d[mt][nt][3] + by);
        }
    }
}

// ============================ tensor-core banded attention (R14, unchanged) ===========
#define AQS     72
#define A_Q     0
#define A_KV    9216
#define A_TILE2 (128 * AQS)
#define A_STAGE2 (2 * A_TILE2)
#define ATTN_SMEM ((A_KV + 2 * A_STAGE2) * 2)   // 92160 B -> 2 CTAs/SM

__global__ __launch_bounds__(256, 2)
void attn_mma_kernel(const __half* __restrict__ q,
                     const __half* __restrict__ k16,
                     const __half* __restrict__ v16,
                     __half* __restrict__ o) {
    extern __shared__ char smem[];
    const uint32_t sbase = smem_u32(smem);
    const int tid = threadIdx.x, lane = tid & 31, w = tid >> 5;
    const int qt = blockIdx.x, h = blockIdx.y, b = blockIdx.z;
    const int qi0 = qt * 128;

    int u_start = 0;
    { int lim = qi0 - 1153; if (lim > 0) u_start = ((lim + 127) >> 7) << 7; }

    {
#pragma unroll
        for (int it = 0; it < 4; it++) {
            int cid = tid + it * 256;
            int r = cid >> 3, qq = cid & 7;
            const void* src = q + ((size_t)(b * 2048 + qi0 + r) << 10) + h * 64 + qq * 8;
            uint32_t dst = sbase + (uint32_t)((A_Q + r * AQS + qq * 8) * 2);
            cp_async16(dst, src);
        }
        cp_commit();
    }

    auto issue_kv = [&](int u0, int s) {
#pragma unroll
        for (int it = 0; it < 8; it++) {
            int cid = tid + it * 256;
            int t = cid >> 10, r = (cid >> 3) & 127, qq = cid & 7;
            const __half* bp = t ? v16 : k16;
            const void* src = bp + ((size_t)(b * 1024 + u0 + r) << 10) + h * 64 + qq * 8;
            uint32_t dst = sbase + (uint32_t)((A_KV + s * A_STAGE2 + t * A_TILE2
                                               + r * AQS + qq * 8) * 2);
            cp_async16(dst, src);
        }
        cp_commit();
    };
    issue_kv(u_start, 0);

    float d[8][4];
#pragma unroll
    for (int nt = 0; nt < 8; nt++)
#pragma unroll
        for (int e = 0; e < 4; e++) d[nt][e] = 0.0f;
    float dl[4] = {0.0f, 0.0f, 0.0f, 0.0f};

    const int i0 = qi0 + w * 16 + (lane >> 2);
    const int i1 = i0 + 8;
    const uint32_t ONES2 = 0x3C003C00u;

    const int nIter = (1024 - u_start) >> 7;
    for (int itn = 0; itn < nIter; itn++) {
        const int ub = u_start + itn * 128;
        const int s  = itn & 1;

        asm volatile("cp.async.wait_group 0;" ::: "memory");
        __syncthreads();
        if (itn + 1 < nIter) issue_kv(ub + 128, s ^ 1);

        const uint32_t stg = sbase + (uint32_t)((A_KV + s * A_STAGE2) * 2);

#pragma unroll
        for (int half = 0; half < 2; half++) {
            const int u0 = ub + half * 64;
            if (u0 + 63 < qi0 - 1026) continue;
            const uint32_t koff = stg + (uint32_t)(half * 64 * AQS * 2);
            const uint32_t vbase = stg + (uint32_t)(A_TILE2 * 2) + (uint32_t)(half * 64 * AQS * 2);

            float s_[8][4];
#pragma unroll
            for (int nt = 0; nt < 8; nt++)
#pragma unroll
                for (int e = 0; e < 4; e++) s_[nt][e] = 0.0f;

#pragma unroll
            for (int ks = 0; ks < 4; ks++) {
                uint32_t af[4];
                ldsm_x4(af[0], af[1], af[2], af[3],
                    sbase + (uint32_t)(((w * 16 + (lane & 15)) * AQS + ks * 16 + (lane >> 4) * 8) * 2));
                const int mrow = lane >> 3;
                uint32_t bf[4][4];
#pragma unroll
                for (int g = 0; g < 4; g++)
                    ldsm_x4(bf[g][0], bf[g][1], bf[g][2], bf[g][3],
                        koff + (uint32_t)(((g * 16 + (mrow & 2) * 4 + (lane & 7)) * AQS
                                          + ks * 16 + (mrow & 1) * 8) * 2));
#pragma unroll
                for (int nt = 0; nt < 8; nt++)
                    mma_f16(s_[nt], af, bf[nt >> 1][(nt & 1) * 2], bf[nt >> 1][(nt & 1) * 2 + 1]);
            }

            const bool t1_all  = (u0 >= qi0 + 125);
            const bool t1_none = (u0 < qi0 - 65);
            const bool t2_all  = (u0 >= qi0 - 899);
            const bool uniform = (t1_all || t1_none) && t2_all;

            uint32_t ph2[8][2];
            if (uniform) {
                const __half2 bias2 = __float2half2_rn(t1_all ? 1.0f : 0.0f);
#pragma unroll
                for (int nt = 0; nt < 8; nt++) {
                    __half2 a0 = h2exp2(__hadd2(__floats2half2_rn(s_[nt][0], s_[nt][1]), bias2));
                    __half2 a1 = h2exp2(__hadd2(__floats2half2_rn(s_[nt][2], s_[nt][3]), bias2));
                    ph2[nt][0] = *reinterpret_cast<uint32_t*>(&a0);
                    ph2[nt][1] = *reinterpret_cast<uint32_t*>(&a1);
                }
            } else {
#pragma unroll
                for (int nt = 0; nt < 8; nt++) {
                    const int uc = u0 + nt * 8 + (lane & 3) * 2;
                    float sv[4];
#pragma unroll
                    for (int e = 0; e < 4; e++) {
                        const int u = uc + (e & 1);
                        const int i = (e < 2) ? i0 : i1;
                        const int mf = (u >= i - 2) + (u >= i - 1026);
                        sv[e] = (mf == 0) ? -1000.0f : s_[nt][e] + (mf == 2 ? 1.0f : 0.0f);
                    }
                    __half2 a0 = h2exp2(__floats2half2_rn(sv[0], sv[1]));
                    __half2 a1 = h2exp2(__floats2half2_rn(sv[2], sv[3]));
                    ph2[nt][0] = *reinterpret_cast<uint32_t*>(&a0);
                    ph2[nt][1] = *reinterpret_cast<uint32_t*>(&a1);
                }
            }

#pragma unroll
            for (int ks = 0; ks < 4; ks++) {
                uint32_t ph[4];
                ph[0] = ph2[2 * ks][0];
                ph[1] = ph2[2 * ks][1];
                ph[2] = ph2[2 * ks + 1][0];
                ph[3] = ph2[2 * ks + 1][1];
                mma_f16(dl, ph, ONES2, ONES2);

                const uint32_t voff = (uint32_t)(((ks * 16 + ((lane >> 3) & 1) * 8 + (lane & 7)) * AQS) * 2)
                                    + (uint32_t)((lane >> 4) * 16);
#pragma unroll
                for (int t = 0; t < 4; t++) {
                    uint32_t vf[4];
                    ldsm_x4_t(vf[0], vf[1], vf[2], vf[3],
                              vbase + voff + (uint32_t)(t * 32));
                    mma_f16(d[2 * t + 0], ph, vf[0], vf[1]);
                    mma_f16(d[2 * t + 1], ph, vf[2], vf[3]);
                }
            }
        }
    }

    const float inv0 = 1.0f / dl[0], inv1 = 1.0f / dl[2];
    const size_t row0 = (size_t)(b * 2048 + qi0 + w * 16 + (lane >> 2));
#pragma unroll
    for (int nt = 0; nt < 8; nt++) {
        const int col = h * 64 + nt * 8 + (lane & 3) * 2;
        *(__half2*)(o + row0 * 1024 + col)       = __floats2half2_rn(d[nt][0] * inv0, d[nt][1] * inv0);
        *(__half2*)(o + (row0 + 8) * 1024 + col) = __floats2half2_rn(d[nt][2] * inv1, d[nt][3] * inv1);
    }
}

// ============================ launch ============================
extern "C" void kernel_launch(void* const* d_in, const int* in_sizes, int n_in,
                              void* d_out, int out_size) {
    const float* x  = (const float*)d_in[0];
    const float* xd = (const float*)d_in[1];
    const float* Wq = (const float*)d_in[2];
    const float* Wk = (const float*)d_in[3];
    const float* Wv = (const float*)d_in[4];
    const float* Wo = (const float*)d_in[5];
    const float* bo = (const float*)d_in[6];
    float* out = (float*)d_out;

    __half *x16, *d16, *q16, *k16, *v16, *ao, *wq, *wk, *wv, *wo;
    cudaGetSymbolAddress((void**)&x16, g_x16);  cudaGetSymbolAddress((void**)&d16, g_d16);
    cudaGetSymbolAddress((void**)&q16, g_q16);  cudaGetSymbolAddress((void**)&k16, g_k16);
    cudaGetSymbolAddress((void**)&v16, g_v16);  cudaGetSymbolAddress((void**)&ao,  g_ao);
    cudaGetSymbolAddress((void**)&wq,  g_wq);   cudaGetSymbolAddress((void**)&wk,  g_wk);
    cudaGetSymbolAddress((void**)&wv,  g_wv);   cudaGetSymbolAddress((void**)&wo,  g_wo);

    cudaFuncSetAttribute(gemm_qkv_kernel, cudaFuncAttributeMaxDynamicSharedMemorySize, G_SMEM);
    cudaFuncSetAttribute(gemm_o_kernel,   cudaFuncAttributeMaxDynamicSharedMemorySize, G_SMEM);
    cudaFuncSetAttribute(attn_mma_kernel, cudaFuncAttributeMaxDynamicSharedMemorySize, ATTN_SMEM);

    const float qscale = 0.125f * 1.44269504088896341f;

    prep_kernel<<<(NPREP + 255) / 256, 256>>>(x, xd, Wq, Wk, Wv, Wo,
                                              x16, d16, wq, wk, wv, wo, qscale);

    gemm_qkv_kernel<<<dim3(8, 64), 256, G_SMEM>>>(x16, d16, wq, wk, wv, q16, k16, v16);

    attn_mma_kernel<<<dim3(16, 16, 2), 256, ATTN_SMEM>>>(q16, k16, v16, ao);

    gemm_o_kernel<<<dim3(8, 32), 256, G_SMEM>>>(ao, wo, out, bo);
}

// round 16
// speedup vs baseline: 1.0534x; 1.0036x over previous
#include <cuda_runtime.h>
#include <cuda_fp16.h>
#include <cstdint>

// ============================ scratch (allocation-free) ============================
__device__ __half g_x16[4096 * 1024];
__device__ __half g_d16[2048 * 1024];
__device__ __half g_q16[4096 * 1024];
__device__ __half g_k16[2048 * 1024];
__device__ __half g_v16[2048 * 1024];
__device__ __half g_ao [4096 * 1024];
__device__ __half g_wq [1024 * 1024];   // natural [k][n] layout, fp16 (Wq pre-scaled)
__device__ __half g_wk [1024 * 1024];
__device__ __half g_wv [1024 * 1024];
__device__ __half g_wo [1024 * 1024];

// ============================ PTX helpers (arch-generic) ============================
__device__ __forceinline__ uint32_t smem_u32(const void* p) {
    uint32_t a;
    asm("{ .reg .u64 t; cvta.to.shared.u64 t, %1; cvt.u32.u64 %0, t; }" : "=r"(a) : "l"(p));
    return a;
}
__device__ __forceinline__ void gdc_wait() {        // PDL: wait for upstream grid's writes
    asm volatile("griddepcontrol.wait;" ::: "memory");
}
__device__ __forceinline__ void ldsm_x4(uint32_t& r0, uint32_t& r1, uint32_t& r2, uint32_t& r3,
                                        uint32_t addr) {
    asm volatile("ldmatrix.sync.aligned.m8n8.x4.shared.b16 {%0,%1,%2,%3}, [%4];"
                 : "=r"(r0), "=r"(r1), "=r"(r2), "=r"(r3) : "r"(addr));
}
__device__ __forceinline__ void ldsm_x4_t(uint32_t& r0, uint32_t& r1, uint32_t& r2, uint32_t& r3,
                                          uint32_t addr) {
    asm volatile("ldmatrix.sync.aligned.m8n8.x4.trans.shared.b16 {%0,%1,%2,%3}, [%4];"
                 : "=r"(r0), "=r"(r1), "=r"(r2), "=r"(r3) : "r"(addr));
}
__device__ __forceinline__ void mma_f16(float* d, const uint32_t* a, uint32_t b0, uint32_t b1) {
    asm volatile("mma.sync.aligned.m16n8k16.row.col.f32.f16.f16.f32 "
                 "{%0,%1,%2,%3}, {%4,%5,%6,%7}, {%8,%9}, {%0,%1,%2,%3};"
                 : "+f"(d[0]), "+f"(d[1]), "+f"(d[2]), "+f"(d[3])
                 : "r"(a[0]), "r"(a[1]), "r"(a[2]), "r"(a[3]), "r"(b0), "r"(b1));
}
__device__ __forceinline__ void cp_async16(uint32_t dst, const void* src) {
    asm volatile("cp.async.cg.shared.global [%0], [%1], 16;" :: "r"(dst), "l"(src) : "memory");
}
__device__ __forceinline__ void cp_commit() {
    asm volatile("cp.async.commit_group;" ::: "memory");
}

// ============================ prep: pure casts (no transpose) ============================
#define NX4 (4096 * 1024 / 4)
#define ND4 (2048 * 1024 / 4)
#define NW4 (1024 * 1024 / 4)
#define NPREP (NX4 + ND4 + 4 * NW4)
__global__ void prep_kernel(const float* __restrict__ x, const float* __restrict__ xd,
                            const float* __restrict__ W0, const float* __restrict__ W1,
                            const float* __restrict__ W2, const float* __restrict__ W3,
                            __half* __restrict__ x16, __half* __restrict__ d16,
                            __half* __restrict__ T0, __half* __restrict__ T1,
                            __half* __restrict__ T2, __half* __restrict__ T3,
                            float w0scale) {
    int i = blockIdx.x * blockDim.x + threadIdx.x;
    if (i >= NPREP) return;
    const float* in; __half* out; int j; float sc = 1.0f;
    if (i < NX4)              { in = x;  out = x16; j = i; }
    else if (i < NX4 + ND4)   { in = xd; out = d16; j = i - NX4; }
    else {
        int wi = i - NX4 - ND4;
        int z  = wi >> 18;
        j      = wi & (NW4 - 1);
        in  = (z == 0) ? W0 : (z == 1) ? W1 : (z == 2) ? W2 : W3;
        out = (z == 0) ? T0 : (z == 1) ? T1 : (z == 2) ? T2 : T3;
        if (z == 0) sc = w0scale;
    }
    float4 v = ((const float4*)in)[j];
    ((__half2*)out)[2 * j + 0] = __floats2half2_rn(v.x * sc, v.y * sc);
    ((__half2*)out)[2 * j + 1] = __floats2half2_rn(v.z * sc, v.w * sc);
}

// ============================ fp16 1-term GEMM core (R15, unchanged) ==================
#define GTS      72
#define BTS      136
#define GA_B     (128 * GTS * 2)
#define GB_B     (64 * BTS * 2)
#define GSTAGE   (GA_B + GB_B)
#define G_SMEM   (3 * GSTAGE)

struct GemmCore {
    __device__ static void run(float d[2][8][4], const __half* A, const __half* Bw,
                               uint32_t sbase, int m0, int n0, int tid) {
        const int lane = tid & 31;
        const int wid  = tid >> 5;
        const int wm   = wid & 3;
        const int wn   = wid >> 2;

        auto issue_loads = [&](int c, int s) {
            const uint32_t abase = sbase + (uint32_t)(s * GSTAGE);
#pragma unroll
            for (int it = 0; it < 4; it++) {
                const int cid = tid + it * 256;
                const int row = cid >> 3, q = cid & 7;
                const void* src = A + ((size_t)(m0 + row) << 10) + c * 64 + q * 8;
                cp_async16(abase + (uint32_t)((row * GTS + q * 8) * 2), src);
            }
            const uint32_t bb = abase + (uint32_t)GA_B;
#pragma unroll
            for (int it = 0; it < 4; it++) {
                const int cid = tid + it * 256;
                const int row = cid >> 4, q = cid & 15;
                const void* src = Bw + ((size_t)(c * 64 + row) << 10) + n0 + q * 8;
                cp_async16(bb + (uint32_t)((row * BTS + q * 8) * 2), src);
            }
            cp_commit();
        };

#pragma unroll
        for (int mt = 0; mt < 2; mt++)
#pragma unroll
            for (int nt = 0; nt < 8; nt++)
#pragma unroll
                for (int e = 0; e < 4; e++) d[mt][nt][e] = 0.0f;

        issue_loads(0, 0);
        issue_loads(1, 1);

        int ld_stage = 2, cur = 0;
        for (int c = 0; c < 16; c++) {
            asm volatile("cp.async.wait_group 1;" ::: "memory");
            __syncthreads();
            if (c + 2 < 16) issue_loads(c + 2, ld_stage);
            else            cp_commit();
            ld_stage = (ld_stage == 2) ? 0 : ld_stage + 1;

            const uint32_t stage = sbase + (uint32_t)(cur * GSTAGE);
            cur = (cur == 2) ? 0 : cur + 1;
            const uint32_t bb = stage + (uint32_t)GA_B;
            const uint32_t bcol = (uint32_t)((lane >> 4) * 16 + wn * 128);
#pragma unroll
            for (int ks = 0; ks < 4; ks++) {
                const int k16 = ks * 16;
                uint32_t af[2][4];
#pragma unroll
                for (int mt = 0; mt < 2; mt++) {
                    uint32_t addr = stage +
                        (uint32_t)(((wm * 32 + mt * 16 + (lane & 15)) * GTS
                                    + k16 + ((lane >> 4) * 8)) * 2);
                    ldsm_x4(af[mt][0], af[mt][1], af[mt][2], af[mt][3], addr);
                }
                const uint32_t brow = bb +
                    (uint32_t)(((k16 + ((lane >> 3) & 1) * 8 + (lane & 7)) * BTS) * 2) + bcol;
#pragma unroll
                for (int t = 0; t < 4; t++) {
                    uint32_t bf[4];
                    ldsm_x4_t(bf[0], bf[1], bf[2], bf[3], brow + (uint32_t)(t * 32));
#pragma unroll
                    for (int mt = 0; mt < 2; mt++) {
                        mma_f16(d[mt][2 * t + 0], af[mt], bf[0], bf[1]);
                        mma_f16(d[mt][2 * t + 1], af[mt], bf[2], bf[3]);
                    }
                }
            }
        }
    }
};

// merged q/k/v projection
__global__ __launch_bounds__(256, 2)
void gemm_qkv_kernel(const __half* __restrict__ x16, const __half* __restrict__ d16,
                     const __half* __restrict__ wq, const __half* __restrict__ wk,
                     const __half* __restrict__ wv,
                     __half* __restrict__ q16, __half* __restrict__ k16,
                     __half* __restrict__ v16) {
    extern __shared__ char smem[];
    const uint32_t sbase = smem_u32(smem);
    const int tid = threadIdx.x;
    const int by  = blockIdx.y;

    const __half* A; const __half* B; __half* C; int m0;
    if (by < 32)      { A = x16; B = wq; C = q16; m0 = by * 128; }
    else if (by < 48) { A = d16; B = wk; C = k16; m0 = (by - 32) * 128; }
    else              { A = d16; B = wv; C = v16; m0 = (by - 48) * 128; }
    const int n0 = blockIdx.x * 128;

    gdc_wait();                 // PDL: upstream prep writes visible

    float d[2][8][4];
    GemmCore::run(d, A, B, sbase, m0, n0, tid);

    const int lane = tid & 31, wid = tid >> 5, wm = wid & 3, wn = wid >> 2;
#pragma unroll
    for (int mt = 0; mt < 2; mt++) {
        const int row0 = m0 + wm * 32 + mt * 16 + (lane >> 2);
#pragma unroll
        for (int nt = 0; nt < 8; nt++) {
            const int col = n0 + wn * 64 + nt * 8 + (lane & 3) * 2;
            *(__half2*)(C + (size_t)row0 * 1024 + col) =
                __floats2half2_rn(d[mt][nt][0], d[mt][nt][1]);
            *(__half2*)(C + (size_t)(row0 + 8) * 1024 + col) =
                __floats2half2_rn(d[mt][nt][2], d[mt][nt][3]);
        }
    }
}

// output projection: fp32 + bias
__global__ __launch_bounds__(256, 2)
void gemm_o_kernel(const __half* __restrict__ A, const __half* __restrict__ B,
                   float* __restrict__ Cf, const float* __restrict__ bias) {
    extern __shared__ char smem[];
    const uint32_t sbase = smem_u32(smem);
    const int tid = threadIdx.x;
    const int m0 = blockIdx.y * 128;
    const int n0 = blockIdx.x * 128;

    gdc_wait();                 // PDL: attn output visible

    float d[2][8][4];
    GemmCore::run(d, A, B, sbase, m0, n0, tid);

    const int lane = tid & 31, wid = tid >> 5, wm = wid & 3, wn = wid >> 2;
#pragma unroll
    for (int mt = 0; mt < 2; mt++) {
        const int row0 = m0 + wm * 32 + mt * 16 + (lane >> 2);
#pragma unroll
        for (int nt = 0; nt < 8; nt++) {
            const int col = n0 + wn * 64 + nt * 8 + (lane & 3) * 2;
            const float bx = bias[col], by = bias[col + 1];
            *(float2*)(Cf + (size_t)row0 * 1024 + col) =
                make_float2(d[mt][nt][0] + bx, d[mt][nt][1] + by);
            *(float2*)(Cf + (size_t)(row0 + 8) * 1024 + col) =
                make_float2(d[mt][nt][2] + bx, d[mt][nt][3] + by);
        }
    }
}

// ============================ tensor-core banded attention (R14 body) =================
#define AQS     72
#define A_Q     0
#define A_KV    9216
#define A_TILE2 (128 * AQS)
#define A_STAGE2 (2 * A_TILE2)
#define ATTN_SMEM ((A_KV + 2 * A_STAGE2) * 2)   // 92160 B -> 2 CTAs/SM

__global__ __launch_bounds__(256, 2)
void attn_mma_kernel(const __half* __restrict__ q,
                     const __half* __restrict__ k16,
                     const __half* __restrict__ v16,
                     __half* __restrict__ o) {
    extern __shared__ char smem[];
    const uint32_t sbase = smem_u32(smem);
    const int tid = threadIdx.x, lane = tid & 31, w = tid >> 5;
    const int qt = blockIdx.x, h = blockIdx.y, b = blockIdx.z;
    const int qi0 = qt * 128;

    int u_start = 0;
    { int lim = qi0 - 1153; if (lim > 0) u_start = ((lim + 127) >> 7) << 7; }

    gdc_wait();                 // PDL: q/k/v projections visible

    {
#pragma unroll
        for (int it = 0; it < 4; it++) {
            int cid = tid + it * 256;
            int r = cid >> 3, qq = cid & 7;
            const void* src = q + ((size_t)(b * 2048 + qi0 + r) << 10) + h * 64 + qq * 8;
            uint32_t dst = sbase + (uint32_t)((A_Q + r * AQS + qq * 8) * 2);
            cp_async16(dst, src);
        }
        cp_commit();
    }

    auto issue_kv = [&](int u0, int s) {
#pragma unroll
        for (int it = 0; it < 8; it++) {
            int cid = tid + it * 256;
            int t = cid >> 10, r = (cid >> 3) & 127, qq = cid & 7;
            const __half* bp = t ? v16 : k16;
            const void* src = bp + ((size_t)(b * 1024 + u0 + r) << 10) + h * 64 + qq * 8;
            uint32_t dst = sbase + (uint32_t)((A_KV + s * A_STAGE2 + t * A_TILE2
                                               + r * AQS + qq * 8) * 2);
            cp_async16(dst, src);
        }
        cp_commit();
    };
    issue_kv(u_start, 0);

    float d[8][4];
#pragma unroll
    for (int nt = 0; nt < 8; nt++)
#pragma unroll
        for (int e = 0; e < 4; e++) d[nt][e] = 0.0f;
    float dl[4] = {0.0f, 0.0f, 0.0f, 0.0f};

    const int i0 = qi0 + w * 16 + (lane >> 2);
    const int i1 = i0 + 8;
    const uint32_t ONES2 = 0x3C003C00u;

    const int nIter = (1024 - u_start) >> 7;
    for (int itn = 0; itn < nIter; itn++) {
        const int ub = u_start + itn * 128;
        const int s  = itn & 1;

        asm volatile("cp.async.wait_group 0;" ::: "memory");
        __syncthreads();
        if (itn + 1 < nIter) issue_kv(ub + 128, s ^ 1);

        const uint32_t stg = sbase + (uint32_t)((A_KV + s * A_STAGE2) * 2);

#pragma unroll
        for (int half = 0; half < 2; half++) {
            const int u0 = ub + half * 64;
            if (u0 + 63 < qi0 - 1026) continue;
            const uint32_t koff = stg + (uint32_t)(half * 64 * AQS * 2);
            const uint32_t vbase = stg + (uint32_t)(A_TILE2 * 2) + (uint32_t)(half * 64 * AQS * 2);

            float s_[8][4];
#pragma unroll
            for (int nt = 0; nt < 8; nt++)
#pragma unroll
                for (int e = 0; e < 4; e++) s_[nt][e] = 0.0f;

#pragma unroll
            for (int ks = 0; ks < 4; ks++) {
                uint32_t af[4];
                ldsm_x4(af[0], af[1], af[2], af[3],
                    sbase + (uint32_t)(((w * 16 + (lane & 15)) * AQS + ks * 16 + (lane >> 4) * 8) * 2));
                const int mrow = lane >> 3;
                uint32_t bf[4][4];
#pragma unroll
                for (int g = 0; g < 4; g++)
                    ldsm_x4(bf[g][0], bf[g][1], bf[g][2], bf[g][3],
                        koff + (uint32_t)(((g * 16 + (mrow & 2) * 4 + (lane & 7)) * AQS
                                          + ks * 16 + (mrow & 1) * 8) * 2));
#pragma unroll
                for (int nt = 0; nt < 8; nt++)
                    mma_f16(s_[nt], af, bf[nt >> 1][(nt & 1) * 2], bf[nt >> 1][(nt & 1) * 2 + 1]);
            }

            const bool t1_all  = (u0 >= qi0 + 125);
            const bool t1_none = (u0 < qi0 - 65);
            const bool t2_all  = (u0 >= qi0 - 899);
            const bool uniform = (t1_all || t1_none) && t2_all;

            uint32_t ph2[8][2];
            if (uniform) {
                const __half2 bias2 = __float2half2_rn(t1_all ? 1.0f : 0.0f);
#pragma unroll
                for (int nt = 0; nt < 8; nt++) {
                    __half2 a0 = h2exp2(__hadd2(__floats2half2_rn(s_[nt][0], s_[nt][1]), bias2));
                    __half2 a1 = h2exp2(__hadd2(__floats2half2_rn(s_[nt][2], s_[nt][3]), bias2));
                    ph2[nt][0] = *reinterpret_cast<uint32_t*>(&a0);
                    ph2[nt][1] = *reinterpret_cast<uint32_t*>(&a1);
                }
            } else {
#pragma unroll
                for (int nt = 0; nt < 8; nt++) {
                    const int uc = u0 + nt * 8 + (lane & 3) * 2;
                    float sv[4];
#pragma unroll
                    for (int e = 0; e < 4; e++) {
                        const int u = uc + (e & 1);
                        const int i = (e < 2) ? i0 : i1;
                        const int mf = (u >= i - 2) + (u >= i - 1026);
                        sv[e] = (mf == 0) ? -1000.0f : s_[nt][e] + (mf == 2 ? 1.0f : 0.0f);
                    }
                    __half2 a0 = h2exp2(__floats2half2_rn(sv[0], sv[1]));
                    __half2 a1 = h2exp2(__floats2half2_rn(sv[2], sv[3]));
                    ph2[nt][0] = *reinterpret_cast<uint32_t*>(&a0);
                    ph2[nt][1] = *reinterpret_cast<uint32_t*>(&a1);
                }
            }

#pragma unroll
            for (int ks = 0; ks < 4; ks++) {
                uint32_t ph[4];
                ph[0] = ph2[2 * ks][0];
                ph[1] = ph2[2 * ks][1];
                ph[2] = ph2[2 * ks + 1][0];
                ph[3] = ph2[2 * ks + 1][1];
                mma_f16(dl, ph, ONES2, ONES2);

                const uint32_t voff = (uint32_t)(((ks * 16 + ((lane >> 3) & 1) * 8 + (lane & 7)) * AQS) * 2)
                                    + (uint32_t)((lane >> 4) * 16);
#pragma unroll
                for (int t = 0; t < 4; t++) {
                    uint32_t vf[4];
                    ldsm_x4_t(vf[0], vf[1], vf[2], vf[3],
                              vbase + voff + (uint32_t)(t * 32));
                    mma_f16(d[2 * t + 0], ph, vf[0], vf[1]);
                    mma_f16(d[2 * t + 1], ph, vf[2], vf[3]);
                }
            }
        }
    }

    const float inv0 = 1.0f / dl[0], inv1 = 1.0f / dl[2];
    const size_t row0 = (size_t)(b * 2048 + qi0 + w * 16 + (lane >> 2));
#pragma unroll
    for (int nt = 0; nt < 8; nt++) {
        const int col = h * 64 + nt * 8 + (lane & 3) * 2;
        *(__half2*)(o + row0 * 1024 + col)       = __floats2half2_rn(d[nt][0] * inv0, d[nt][1] * inv0);
        *(__half2*)(o + (row0 + 8) * 1024 + col) = __floats2half2_rn(d[nt][2] * inv1, d[nt][3] * inv1);
    }
}

// ============================ launch (PDL-chained) ============================
extern "C" void kernel_launch(void* const* d_in, const int* in_sizes, int n_in,
                              void* d_out, int out_size) {
    const float* x  = (const float*)d_in[0];
    const float* xd = (const float*)d_in[1];
    const float* Wq = (const float*)d_in[2];
    const float* Wk = (const float*)d_in[3];
    const float* Wv = (const float*)d_in[4];
    const float* Wo = (const float*)d_in[5];
    const float* bo = (const float*)d_in[6];
    float* out = (float*)d_out;

    __half *x16, *d16, *q16, *k16, *v16, *ao, *wq, *wk, *wv, *wo;
    cudaGetSymbolAddress((void**)&x16, g_x16);  cudaGetSymbolAddress((void**)&d16, g_d16);
    cudaGetSymbolAddress((void**)&q16, g_q16);  cudaGetSymbolAddress((void**)&k16, g_k16);
    cudaGetSymbolAddress((void**)&v16, g_v16);  cudaGetSymbolAddress((void**)&ao,  g_ao);
    cudaGetSymbolAddress((void**)&wq,  g_wq);   cudaGetSymbolAddress((void**)&wk,  g_wk);
    cudaGetSymbolAddress((void**)&wv,  g_wv);   cudaGetSymbolAddress((void**)&wo,  g_wo);

    cudaFuncSetAttribute(gemm_qkv_kernel, cudaFuncAttributeMaxDynamicSharedMemorySize, G_SMEM);
    cudaFuncSetAttribute(gemm_o_kernel,   cudaFuncAttributeMaxDynamicSharedMemorySize, G_SMEM);
    cudaFuncSetAttribute(attn_mma_kernel, cudaFuncAttributeMaxDynamicSharedMemorySize, ATTN_SMEM);

    const float qscale = 0.125f * 1.44269504088896341f;

    prep_kernel<<<(NPREP + 255) / 256, 256>>>(x, xd, Wq, Wk, Wv, Wo,
                                              x16, d16, wq, wk, wv, wo, qscale);

    cudaLaunchAttribute pdl[1];
    pdl[0].id = cudaLaunchAttributeProgrammaticStreamSerialization;
    pdl[0].val.programmaticStreamSerializationAllowed = 1;

    {
        cudaLaunchConfig_t cfg = {};
        cfg.gridDim = dim3(8, 64); cfg.blockDim = dim3(256);
        cfg.dynamicSmemBytes = G_SMEM; cfg.stream = 0;
        cfg.attrs = pdl; cfg.numAttrs = 1;
        cudaLaunchKernelEx(&cfg, gemm_qkv_kernel, (const __half*)x16, (const __half*)d16,
                           (const __half*)wq, (const __half*)wk, (const __half*)wv,
                           q16, k16, v16);
    }
    {
        cudaLaunchConfig_t cfg = {};
        cfg.gridDim = dim3(16, 16, 2); cfg.blockDim = dim3(256);
        cfg.dynamicSmemBytes = ATTN_SMEM; cfg.stream = 0;
        cfg.attrs = pdl; cfg.numAttrs = 1;
        cudaLaunchKernelEx(&cfg, attn_mma_kernel, (const __half*)q16, (const __half*)k16,
                           (const __half*)v16, ao);
    }
    {
        cudaLaunchConfig_t cfg = {};
        cfg.gridDim = dim3(8, 32); cfg.blockDim = dim3(256);
        cfg.dynamicSmemBytes = G_SMEM; cfg.stream = 0;
        cfg.attrs = pdl; cfg.numAttrs = 1;
        cudaLaunchKernelEx(&cfg, gemm_o_kernel, (const __half*)ao, (const __half*)wo, out, bo);
    }
}

// round 17
// speedup vs baseline: 1.1107x; 1.0544x over previous
#include <cuda_runtime.h>
#include <cuda_fp16.h>
#include <cstdint>

// ============================ scratch (allocation-free) ============================
__device__ __half g_x16[4096 * 1024];
__device__ __half g_d16[2048 * 1024];
__device__ __half g_q16[4096 * 1024];
__device__ __half g_k16[2048 * 1024];
__device__ __half g_v16[2048 * 1024];
__device__ __half g_ao [4096 * 1024];
__device__ __half g_wq [1024 * 1024];   // natural [k][n] layout, fp16 (Wq pre-scaled)
__device__ __half g_wk [1024 * 1024];
__device__ __half g_wv [1024 * 1024];
__device__ __half g_wo [1024 * 1024];

// ============================ PTX helpers (arch-generic) ============================
__device__ __forceinline__ uint32_t smem_u32(const void* p) {
    uint32_t a;
    asm("{ .reg .u64 t; cvta.to.shared.u64 t, %1; cvt.u32.u64 %0, t; }" : "=r"(a) : "l"(p));
    return a;
}
__device__ __forceinline__ void gdc_wait() {
    asm volatile("griddepcontrol.wait;" ::: "memory");
}
__device__ __forceinline__ void ldsm_x4(uint32_t& r0, uint32_t& r1, uint32_t& r2, uint32_t& r3,
                                        uint32_t addr) {
    asm volatile("ldmatrix.sync.aligned.m8n8.x4.shared.b16 {%0,%1,%2,%3}, [%4];"
                 : "=r"(r0), "=r"(r1), "=r"(r2), "=r"(r3) : "r"(addr));
}
__device__ __forceinline__ void ldsm_x4_t(uint32_t& r0, uint32_t& r1, uint32_t& r2, uint32_t& r3,
                                          uint32_t addr) {
    asm volatile("ldmatrix.sync.aligned.m8n8.x4.trans.shared.b16 {%0,%1,%2,%3}, [%4];"
                 : "=r"(r0), "=r"(r1), "=r"(r2), "=r"(r3) : "r"(addr));
}
__device__ __forceinline__ void mma_f16(float* d, const uint32_t* a, uint32_t b0, uint32_t b1) {
    asm volatile("mma.sync.aligned.m16n8k16.row.col.f32.f16.f16.f32 "
                 "{%0,%1,%2,%3}, {%4,%5,%6,%7}, {%8,%9}, {%0,%1,%2,%3};"
                 : "+f"(d[0]), "+f"(d[1]), "+f"(d[2]), "+f"(d[3])
                 : "r"(a[0]), "r"(a[1]), "r"(a[2]), "r"(a[3]), "r"(b0), "r"(b1));
}
__device__ __forceinline__ void cp_async16(uint32_t dst, const void* src) {
    asm volatile("cp.async.cg.shared.global [%0], [%1], 16;" :: "r"(dst), "l"(src) : "memory");
}
__device__ __forceinline__ void cp_commit() {
    asm volatile("cp.async.commit_group;" ::: "memory");
}

// ============================ prep: pure casts (no transpose) ============================
#define NX4 (4096 * 1024 / 4)
#define ND4 (2048 * 1024 / 4)
#define NW4 (1024 * 1024 / 4)
#define NPREP (NX4 + ND4 + 4 * NW4)
__global__ void prep_kernel(const float* __restrict__ x, const float* __restrict__ xd,
                            const float* __restrict__ W0, const float* __restrict__ W1,
                            const float* __restrict__ W2, const float* __restrict__ W3,
                            __half* __restrict__ x16, __half* __restrict__ d16,
                            __half* __restrict__ T0, __half* __restrict__ T1,
                            __half* __restrict__ T2, __half* __restrict__ T3,
                            float w0scale) {
    int i = blockIdx.x * blockDim.x + threadIdx.x;
    if (i >= NPREP) return;
    const float* in; __half* out; int j; float sc = 1.0f;
    if (i < NX4)              { in = x;  out = x16; j = i; }
    else if (i < NX4 + ND4)   { in = xd; out = d16; j = i - NX4; }
    else {
        int wi = i - NX4 - ND4;
        int z  = wi >> 18;
        j      = wi & (NW4 - 1);
        in  = (z == 0) ? W0 : (z == 1) ? W1 : (z == 2) ? W2 : W3;
        out = (z == 0) ? T0 : (z == 1) ? T1 : (z == 2) ? T2 : T3;
        if (z == 0) sc = w0scale;
    }
    float4 v = ((const float4*)in)[j];
    ((__half2*)out)[2 * j + 0] = __floats2half2_rn(v.x * sc, v.y * sc);
    ((__half2*)out)[2 * j + 1] = __floats2half2_rn(v.z * sc, v.w * sc);
}

// ============================ fp16 1-term GEMM core (R15, unchanged) ==================
#define GTS      72
#define BTS      136
#define GA_B     (128 * GTS * 2)
#define GB_B     (64 * BTS * 2)
#define GSTAGE   (GA_B + GB_B)
#define G_SMEM   (3 * GSTAGE)

struct GemmCore {
    __device__ static void run(float d[2][8][4], const __half* A, const __half* Bw,
                               uint32_t sbase, int m0, int n0, int tid) {
        const int lane = tid & 31;
        const int wid  = tid >> 5;
        const int wm   = wid & 3;
        const int wn   = wid >> 2;

        auto issue_loads = [&](int c, int s) {
            const uint32_t abase = sbase + (uint32_t)(s * GSTAGE);
#pragma unroll
            for (int it = 0; it < 4; it++) {
                const int cid = tid + it * 256;
                const int row = cid >> 3, q = cid & 7;
                const void* src = A + ((size_t)(m0 + row) << 10) + c * 64 + q * 8;
                cp_async16(abase + (uint32_t)((row * GTS + q * 8) * 2), src);
            }
            const uint32_t bb = abase + (uint32_t)GA_B;
#pragma unroll
            for (int it = 0; it < 4; it++) {
                const int cid = tid + it * 256;
                const int row = cid >> 4, q = cid & 15;
                const void* src = Bw + ((size_t)(c * 64 + row) << 10) + n0 + q * 8;
                cp_async16(bb + (uint32_t)((row * BTS + q * 8) * 2), src);
            }
            cp_commit();
        };

#pragma unroll
        for (int mt = 0; mt < 2; mt++)
#pragma unroll
            for (int nt = 0; nt < 8; nt++)
#pragma unroll
                for (int e = 0; e < 4; e++) d[mt][nt][e] = 0.0f;

        issue_loads(0, 0);
        issue_loads(1, 1);

        int ld_stage = 2, cur = 0;
        for (int c = 0; c < 16; c++) {
            asm volatile("cp.async.wait_group 1;" ::: "memory");
            __syncthreads();
            if (c + 2 < 16) issue_loads(c + 2, ld_stage);
            else            cp_commit();
            ld_stage = (ld_stage == 2) ? 0 : ld_stage + 1;

            const uint32_t stage = sbase + (uint32_t)(cur * GSTAGE);
            cur = (cur == 2) ? 0 : cur + 1;
            const uint32_t bb = stage + (uint32_t)GA_B;
            const uint32_t bcol = (uint32_t)((lane >> 4) * 16 + wn * 128);
#pragma unroll
            for (int ks = 0; ks < 4; ks++) {
                const int k16 = ks * 16;
                uint32_t af[2][4];
#pragma unroll
                for (int mt = 0; mt < 2; mt++) {
                    uint32_t addr = stage +
                        (uint32_t)(((wm * 32 + mt * 16 + (lane & 15)) * GTS
                                    + k16 + ((lane >> 4) * 8)) * 2);
                    ldsm_x4(af[mt][0], af[mt][1], af[mt][2], af[mt][3], addr);
                }
                const uint32_t brow = bb +
                    (uint32_t)(((k16 + ((lane >> 3) & 1) * 8 + (lane & 7)) * BTS) * 2) + bcol;
#pragma unroll
                for (int t = 0; t < 4; t++) {
                    uint32_t bf[4];
                    ldsm_x4_t(bf[0], bf[1], bf[2], bf[3], brow + (uint32_t)(t * 32));
#pragma unroll
                    for (int mt = 0; mt < 2; mt++) {
                        mma_f16(d[mt][2 * t + 0], af[mt], bf[0], bf[1]);
                        mma_f16(d[mt][2 * t + 1], af[mt], bf[2], bf[3]);
                    }
                }
            }
        }
    }
};

// merged q/k/v projection
__global__ __launch_bounds__(256, 2)
void gemm_qkv_kernel(const __half* __restrict__ x16, const __half* __restrict__ d16,
                     const __half* __restrict__ wq, const __half* __restrict__ wk,
                     const __half* __restrict__ wv,
                     __half* __restrict__ q16, __half* __restrict__ k16,
                     __half* __restrict__ v16) {
    extern __shared__ char smem[];
    const uint32_t sbase = smem_u32(smem);
    const int tid = threadIdx.x;
    const int by  = blockIdx.y;

    const __half* A; const __half* B; __half* C; int m0;
    if (by < 32)      { A = x16; B = wq; C = q16; m0 = by * 128; }
    else if (by < 48) { A = d16; B = wk; C = k16; m0 = (by - 32) * 128; }
    else              { A = d16; B = wv; C = v16; m0 = (by - 48) * 128; }
    const int n0 = blockIdx.x * 128;

    gdc_wait();

    float d[2][8][4];
    GemmCore::run(d, A, B, sbase, m0, n0, tid);

    const int lane = tid & 31, wid = tid >> 5, wm = wid & 3, wn = wid >> 2;
#pragma unroll
    for (int mt = 0; mt < 2; mt++) {
        const int row0 = m0 + wm * 32 + mt * 16 + (lane >> 2);
#pragma unroll
        for (int nt = 0; nt < 8; nt++) {
            const int col = n0 + wn * 64 + nt * 8 + (lane & 3) * 2;
            *(__half2*)(C + (size_t)row0 * 1024 + col) =
                __floats2half2_rn(d[mt][nt][0], d[mt][nt][1]);
            *(__half2*)(C + (size_t)(row0 + 8) * 1024 + col) =
                __floats2half2_rn(d[mt][nt][2], d[mt][nt][3]);
        }
    }
}

// output projection: fp32 + bias
__global__ __launch_bounds__(256, 2)
void gemm_o_kernel(const __half* __restrict__ A, const __half* __restrict__ B,
                   float* __restrict__ Cf, const float* __restrict__ bias) {
    extern __shared__ char smem[];
    const uint32_t sbase = smem_u32(smem);
    const int tid = threadIdx.x;
    const int m0 = blockIdx.y * 128;
    const int n0 = blockIdx.x * 128;

    gdc_wait();

    float d[2][8][4];
    GemmCore::run(d, A, B, sbase, m0, n0, tid);

    const int lane = tid & 31, wid = tid >> 5, wm = wid & 3, wn = wid >> 2;
#pragma unroll
    for (int mt = 0; mt < 2; mt++) {
        const int row0 = m0 + wm * 32 + mt * 16 + (lane >> 2);
#pragma unroll
        for (int nt = 0; nt < 8; nt++) {
            const int col = n0 + wn * 64 + nt * 8 + (lane & 3) * 2;
            const float bx = bias[col], by = bias[col + 1];
            *(float2*)(Cf + (size_t)row0 * 1024 + col) =
                make_float2(d[mt][nt][0] + bx, d[mt][nt][1] + by);
            *(float2*)(Cf + (size_t)(row0 + 8) * 1024 + col) =
                make_float2(d[mt][nt][2] + bx, d[mt][nt][3] + by);
        }
    }
}

// ============================ tensor-core banded attention ============================
// R14 body; LPT grid remap: x = h*2+b (fast), y = qt (slow) so heavy tiles dispatch first.
#define AQS     72
#define A_Q     0
#define A_KV    9216
#define A_TILE2 (128 * AQS)
#define A_STAGE2 (2 * A_TILE2)
#define ATTN_SMEM ((A_KV + 2 * A_STAGE2) * 2)   // 92160 B -> 2 CTAs/SM

__global__ __launch_bounds__(256, 2)
void attn_mma_kernel(const __half* __restrict__ q,
                     const __half* __restrict__ k16,
                     const __half* __restrict__ v16,
                     __half* __restrict__ o) {
    extern __shared__ char smem[];
    const uint32_t sbase = smem_u32(smem);
    const int tid = threadIdx.x, lane = tid & 31, w = tid >> 5;
    const int h  = blockIdx.x >> 1;        // LPT remap
    const int b  = blockIdx.x & 1;
    const int qt = blockIdx.y;
    const int qi0 = qt * 128;

    int u_start = 0;
    { int lim = qi0 - 1153; if (lim > 0) u_start = ((lim + 127) >> 7) << 7; }

    gdc_wait();

    {
#pragma unroll
        for (int it = 0; it < 4; it++) {
            int cid = tid + it * 256;
            int r = cid >> 3, qq = cid & 7;
            const void* src = q + ((size_t)(b * 2048 + qi0 + r) << 10) + h * 64 + qq * 8;
            uint32_t dst = sbase + (uint32_t)((A_Q + r * AQS + qq * 8) * 2);
            cp_async16(dst, src);
        }
        cp_commit();
    }

    auto issue_kv = [&](int u0, int s) {
#pragma unroll
        for (int it = 0; it < 8; it++) {
            int cid = tid + it * 256;
            int t = cid >> 10, r = (cid >> 3) & 127, qq = cid & 7;
            const __half* bp = t ? v16 : k16;
            const void* src = bp + ((size_t)(b * 1024 + u0 + r) << 10) + h * 64 + qq * 8;
            uint32_t dst = sbase + (uint32_t)((A_KV + s * A_STAGE2 + t * A_TILE2
                                               + r * AQS + qq * 8) * 2);
            cp_async16(dst, src);
        }
        cp_commit();
    };
    issue_kv(u_start, 0);

    float d[8][4];
#pragma unroll
    for (int nt = 0; nt < 8; nt++)
#pragma unroll
        for (int e = 0; e < 4; e++) d[nt][e] = 0.0f;
    float dl[4] = {0.0f, 0.0f, 0.0f, 0.0f};

    const int i0 = qi0 + w * 16 + (lane >> 2);
    const int i1 = i0 + 8;
    const uint32_t ONES2 = 0x3C003C00u;

    const int nIter = (1024 - u_start) >> 7;
    for (int itn = 0; itn < nIter; itn++) {
        const int ub = u_start + itn * 128;
        const int s  = itn & 1;

        asm volatile("cp.async.wait_group 0;" ::: "memory");
        __syncthreads();
        if (itn + 1 < nIter) issue_kv(ub + 128, s ^ 1);

        const uint32_t stg = sbase + (uint32_t)((A_KV + s * A_STAGE2) * 2);

#pragma unroll
        for (int half = 0; half < 2; half++) {
            const int u0 = ub + half * 64;
            if (u0 + 63 < qi0 - 1026) continue;
            const uint32_t koff = stg + (uint32_t)(half * 64 * AQS * 2);
            const uint32_t vbase = stg + (uint32_t)(A_TILE2 * 2) + (uint32_t)(half * 64 * AQS * 2);

            float s_[8][4];
#pragma unroll
            for (int nt = 0; nt < 8; nt++)
#pragma unroll
                for (int e = 0; e < 4; e++) s_[nt][e] = 0.0f;

#pragma unroll
            for (int ks = 0; ks < 4; ks++) {
                uint32_t af[4];
                ldsm_x4(af[0], af[1], af[2], af[3],
                    sbase + (uint32_t)(((w * 16 + (lane & 15)) * AQS + ks * 16 + (lane >> 4) * 8) * 2));
                const int mrow = lane >> 3;
                uint32_t bf[4][4];
#pragma unroll
                for (int g = 0; g < 4; g++)
                    ldsm_x4(bf[g][0], bf[g][1], bf[g][2], bf[g][3],
                        koff + (uint32_t)(((g * 16 + (mrow & 2) * 4 + (lane & 7)) * AQS
                                          + ks * 16 + (mrow & 1) * 8) * 2));
#pragma unroll
                for (int nt = 0; nt < 8; nt++)
                    mma_f16(s_[nt], af, bf[nt >> 1][(nt & 1) * 2], bf[nt >> 1][(nt & 1) * 2 + 1]);
            }

            const bool t1_all  = (u0 >= qi0 + 125);
            const bool t1_none = (u0 < qi0 - 65);
            const bool t2_all  = (u0 >= qi0 - 899);
            const bool uniform = (t1_all || t1_none) && t2_all;

            uint32_t ph2[8][2];
            if (uniform) {
                const __half2 bias2 = __float2half2_rn(t1_all ? 1.0f : 0.0f);
#pragma unroll
                for (int nt = 0; nt < 8; nt++) {
                    __half2 a0 = h2exp2(__hadd2(__floats2half2_rn(s_[nt][0], s_[nt][1]), bias2));
                    __half2 a1 = h2exp2(__hadd2(__floats2half2_rn(s_[nt][2], s_[nt][3]), bias2));
                    ph2[nt][0] = *reinterpret_cast<uint32_t*>(&a0);
                    ph2[nt][1] = *reinterpret_cast<uint32_t*>(&a1);
                }
            } else {
#pragma unroll
                for (int nt = 0; nt < 8; nt++) {
                    const int uc = u0 + nt * 8 + (lane & 3) * 2;
                    float sv[4];
#pragma unroll
                    for (int e = 0; e < 4; e++) {
                        const int u = uc + (e & 1);
                        const int i = (e < 2) ? i0 : i1;
                        const int mf = (u >= i - 2) + (u >= i - 1026);
                        sv[e] = (mf == 0) ? -1000.0f : s_[nt][e] + (mf == 2 ? 1.0f : 0.0f);
                    }
                    __half2 a0 = h2exp2(__floats2half2_rn(sv[0], sv[1]));
                    __half2 a1 = h2exp2(__floats2half2_rn(sv[2], sv[3]));
                    ph2[nt][0] = *reinterpret_cast<uint32_t*>(&a0);
                    ph2[nt][1] = *reinterpret_cast<uint32_t*>(&a1);
                }
            }

#pragma unroll
            for (int ks = 0; ks < 4; ks++) {
                uint32_t ph[4];
                ph[0] = ph2[2 * ks][0];
                ph[1] = ph2[2 * ks][1];
                ph[2] = ph2[2 * ks + 1][0];
                ph[3] = ph2[2 * ks + 1][1];
                mma_f16(dl, ph, ONES2, ONES2);

                const uint32_t voff = (uint32_t)(((ks * 16 + ((lane >> 3) & 1) * 8 + (lane & 7)) * AQS) * 2)
                                    + (uint32_t)((lane >> 4) * 16);
#pragma unroll
                for (int t = 0; t < 4; t++) {
                    uint32_t vf[4];
                    ldsm_x4_t(vf[0], vf[1], vf[2], vf[3],
                              vbase + voff + (uint32_t)(t * 32));
                    mma_f16(d[2 * t + 0], ph, vf[0], vf[1]);
                    mma_f16(d[2 * t + 1], ph, vf[2], vf[3]);
                }
            }
        }
    }

    const float inv0 = 1.0f / dl[0], inv1 = 1.0f / dl[2];
    const size_t row0 = (size_t)(b * 2048 + qi0 + w * 16 + (lane >> 2));
#pragma unroll
    for (int nt = 0; nt < 8; nt++) {
        const int col = h * 64 + nt * 8 + (lane & 3) * 2;
        *(__half2*)(o + row0 * 1024 + col)       = __floats2half2_rn(d[nt][0] * inv0, d[nt][1] * inv0);
        *(__half2*)(o + (row0 + 8) * 1024 + col) = __floats2half2_rn(d[nt][2] * inv1, d[nt][3] * inv1);
    }
}

// ============================ launch (PDL-chained) ============================
extern "C" void kernel_launch(void* const* d_in, const int* in_sizes, int n_in,
                              void* d_out, int out_size) {
    const float* x  = (const float*)d_in[0];
    const float* xd = (const float*)d_in[1];
    const float* Wq = (const float*)d_in[2];
    const float* Wk = (const float*)d_in[3];
    const float* Wv = (const float*)d_in[4];
    const float* Wo = (const float*)d_in[5];
    const float* bo = (const float*)d_in[6];
    float* out = (float*)d_out;

    __half *x16, *d16, *q16, *k16, *v16, *ao, *wq, *wk, *wv, *wo;
    cudaGetSymbolAddress((void**)&x16, g_x16);  cudaGetSymbolAddress((void**)&d16, g_d16);
    cudaGetSymbolAddress((void**)&q16, g_q16);  cudaGetSymbolAddress((void**)&k16, g_k16);
    cudaGetSymbolAddress((void**)&v16, g_v16);  cudaGetSymbolAddress((void**)&ao,  g_ao);
    cudaGetSymbolAddress((void**)&wq,  g_wq);   cudaGetSymbolAddress((void**)&wk,  g_wk);
    cudaGetSymbolAddress((void**)&wv,  g_wv);   cudaGetSymbolAddress((void**)&wo,  g_wo);

    cudaFuncSetAttribute(gemm_qkv_kernel, cudaFuncAttributeMaxDynamicSharedMemorySize, G_SMEM);
    cudaFuncSetAttribute(gemm_o_kernel,   cudaFuncAttributeMaxDynamicSharedMemorySize, G_SMEM);
    cudaFuncSetAttribute(attn_mma_kernel, cudaFuncAttributeMaxDynamicSharedMemorySize, ATTN_SMEM);

    const float qscale = 0.125f * 1.44269504088896341f;

    prep_kernel<<<(NPREP + 255) / 256, 256>>>(x, xd, Wq, Wk, Wv, Wo,
                                              x16, d16, wq, wk, wv, wo, qscale);

    cudaLaunchAttribute pdl[1];
    pdl[0].id = cudaLaunchAttributeProgrammaticStreamSerialization;
    pdl[0].val.programmaticStreamSerializationAllowed = 1;

    {
        cudaLaunchConfig_t cfg = {};
        cfg.gridDim = dim3(8, 64); cfg.blockDim = dim3(256);
        cfg.dynamicSmemBytes = G_SMEM; cfg.stream = 0;
        cfg.attrs = pdl; cfg.numAttrs = 1;
        cudaLaunchKernelEx(&cfg, gemm_qkv_kernel, (const __half*)x16, (const __half*)d16,
                           (const __half*)wq, (const __half*)wk, (const __half*)wv,
                           q16, k16, v16);
    }
    {
        cudaLaunchConfig_t cfg = {};
        cfg.gridDim = dim3(32, 16); cfg.blockDim = dim3(256);   // LPT: (h,b) fast, qt slow
        cfg.dynamicSmemBytes = ATTN_SMEM; cfg.stream = 0;
        cfg.attrs = pdl; cfg.numAttrs = 1;
        cudaLaunchKernelEx(&cfg, attn_mma_kernel, (const __half*)q16, (const __half*)k16,
                           (const __half*)v16, ao);
    }
    {
        cudaLaunchConfig_t cfg = {};
        cfg.gridDim = dim3(8, 32); cfg.blockDim = dim3(256);
        cfg.dynamicSmemBytes = G_SMEM; cfg.stream = 0;
        cfg.attrs = pdl; cfg.numAttrs = 1;
        cudaLaunchKernelEx(&cfg, gemm_o_kernel, (const __half*)ao, (const __half*)wo, out, bo);
    }
}